// round 12
// baseline (speedup 1.0000x reference)
#include <cuda_runtime.h>
#include <cuda_fp16.h>
#include <math.h>
#include <float.h>
#include <stdint.h>

#define NN 50000
#define EE 400000
#define EPSV 1e-5f

// ---------------- scratch ----------------
__device__ __half g_h[(size_t)NN * 512];
__device__ float g_io0[(size_t)NN * 128];
__device__ float g_io1[(size_t)NN * 128];   // also reused as agg[NN][16]
__device__ float g_ls[NN * 4];
__device__ float g_ld[NN * 4];
__device__ float g_logits[NN];
__device__ float g_bn[448];
__device__ float g_part[256];
__device__ int   g_deg[NN];
__device__ int   g_off[NN + 1];
__device__ int   g_cur[NN];
__device__ int   g_srcs[EE + NN];
__device__ int   g_bsum[256];

// ---------------- threefry2x32 (partitionable xor bits) ----------------
__device__ __forceinline__ unsigned rotl32d(unsigned v, int r) {
    return __funnelshift_l(v, v, r);
}
__device__ __forceinline__ unsigned tf_xor(unsigned k0, unsigned k1, unsigned x0, unsigned x1) {
    unsigned k2 = k0 ^ k1 ^ 0x1BD11BDAu;
    x0 += k0; x1 += k1;
#define TF_R(r) { x0 += x1; x1 = rotl32d(x1, r); x1 ^= x0; }
    TF_R(13) TF_R(15) TF_R(26) TF_R(6)   x0 += k1; x1 += k2 + 1u;
    TF_R(17) TF_R(29) TF_R(16) TF_R(24)  x0 += k2; x1 += k0 + 2u;
    TF_R(13) TF_R(15) TF_R(26) TF_R(6)   x0 += k0; x1 += k1 + 3u;
    TF_R(17) TF_R(29) TF_R(16) TF_R(24)  x0 += k1; x1 += k2 + 4u;
    TF_R(13) TF_R(15) TF_R(26) TF_R(6)   x0 += k2; x1 += k0 + 5u;
#undef TF_R
    return x0 ^ x1;
}
static inline unsigned rotl32h(unsigned v, int r) { return (v << r) | (v >> (32 - r)); }
static void tf_host(unsigned k0, unsigned k1, unsigned x0, unsigned x1,
                    unsigned* o0, unsigned* o1) {
    unsigned k2 = k0 ^ k1 ^ 0x1BD11BDAu;
    x0 += k0; x1 += k1;
#define TF_RH(r) { x0 += x1; x1 = rotl32h(x1, r); x1 ^= x0; }
    TF_RH(13) TF_RH(15) TF_RH(26) TF_RH(6)   x0 += k1; x1 += k2 + 1u;
    TF_RH(17) TF_RH(29) TF_RH(16) TF_RH(24)  x0 += k2; x1 += k0 + 2u;
    TF_RH(13) TF_RH(15) TF_RH(26) TF_RH(6)   x0 += k0; x1 += k1 + 3u;
    TF_RH(17) TF_RH(29) TF_RH(16) TF_RH(24)  x0 += k1; x1 += k2 + 4u;
    TF_RH(13) TF_RH(15) TF_RH(26) TF_RH(6)   x0 += k2; x1 += k0 + 5u;
#undef TF_RH
    *o0 = x0; *o1 = x1;
}

// ---------------- init ----------------
__global__ void k_init(int* __restrict__ deg, float* __restrict__ bn, int n) {
    int i = blockIdx.x * blockDim.x + threadIdx.x;
    if (i < n) deg[i] = 1;
    if (i < 448) bn[i] = 0.f;
}
__global__ void k_count(const int* __restrict__ dst, int e, int* deg) {
    int i = blockIdx.x * blockDim.x + threadIdx.x;
    if (i < e) atomicAdd(&deg[dst[i]], 1);
}

// ---------------- 3-stage scan ----------------
__global__ void k_scan1(const int* __restrict__ in, int* __restrict__ out,
                        int* __restrict__ bsum, int n) {
    __shared__ int sh[256];
    int i = blockIdx.x * 256 + threadIdx.x;
    int t = threadIdx.x;
    int v = (i < n) ? in[i] : 0;
    sh[t] = v;
    __syncthreads();
#pragma unroll
    for (int o = 1; o < 256; o <<= 1) {
        int add = (t >= o) ? sh[t - o] : 0;
        __syncthreads();
        sh[t] += add;
        __syncthreads();
    }
    if (i < n) out[i] = sh[t] - v;
    if (t == 255) bsum[blockIdx.x] = sh[255];
}
__global__ void k_scan1_cond(const float* __restrict__ x, int* __restrict__ out,
                             int* __restrict__ bsum, int n) {
    __shared__ int sh[256];
    int i = blockIdx.x * 256 + threadIdx.x;
    int t = threadIdx.x;
    int v = 0;
    if (i < n) v = (x[i * 6 + 2] == 1.0f && x[i * 6 + 5] == 0.0f) ? 1 : 0;
    sh[t] = v;
    __syncthreads();
#pragma unroll
    for (int o = 1; o < 256; o <<= 1) {
        int add = (t >= o) ? sh[t - o] : 0;
        __syncthreads();
        sh[t] += add;
        __syncthreads();
    }
    if (i < n) out[i] = sh[t] - v;
    if (t == 255) bsum[blockIdx.x] = sh[255];
}
__global__ void k_scan2(int* __restrict__ bsum, int nb, int* __restrict__ total) {
    __shared__ int sh[256];
    int t = threadIdx.x;
    int v = (t < nb) ? bsum[t] : 0;
    sh[t] = v;
    __syncthreads();
#pragma unroll
    for (int o = 1; o < 256; o <<= 1) {
        int add = (t >= o) ? sh[t - o] : 0;
        __syncthreads();
        sh[t] += add;
        __syncthreads();
    }
    if (t < nb) bsum[t] = sh[t] - v;
    if (t == 0 && total) *total = sh[255];
}
template <int MODE>
__global__ void k_scan3(int* __restrict__ out, const int* __restrict__ bsum,
                        int* __restrict__ cur, int n) {
    int i = blockIdx.x * 256 + threadIdx.x;
    if (i < n) {
        int v = out[i] + bsum[blockIdx.x];
        out[i] = v;
        cur[i] = MODE ? 0 : v;
    }
}
__global__ void k_scatter(const int* __restrict__ src, const int* __restrict__ dst,
                          int e, int n, int* cur, int* __restrict__ outsrc) {
    int i = blockIdx.x * blockDim.x + threadIdx.x;
    if (i < e) {
        int p = atomicAdd(&cur[dst[i]], 1);
        outsrc[p] = src[i];
    } else if (i < e + n) {
        int nd = i - e;
        int p = atomicAdd(&cur[nd], 1);
        outsrc[p] = nd;
    }
}
__global__ void k_idx_scatter(const float* __restrict__ x, const int* __restrict__ pos,
                              int* __restrict__ idx, int n) {
    int i = blockIdx.x * blockDim.x + threadIdx.x;
    if (i < n && x[i * 6 + 2] == 1.0f && x[i * 6 + 5] == 0.0f) idx[pos[i]] = i;
}

__device__ __forceinline__ float lrelu02(float v) { return v > 0.f ? v : 0.2f * v; }

// ---------------- layer-1 coef with in-block fold ----------------
__global__ void k_coef1(const float* __restrict__ x, const float* __restrict__ W1,
                        const float* __restrict__ as1, const float* __restrict__ ad1,
                        float* __restrict__ ls, float* __restrict__ ld, int n) {
    __shared__ float fold[32];
    int t = threadIdx.x;
    if (t < 32) {
        int h = (t & 15) >> 2, k = t & 3;
        const float* a = (t < 16) ? as1 : ad1;
        float s = 0.f;
        for (int c = 0; c < 128; c++)
            s = fmaf(W1[k * 512 + h * 128 + c], a[h * 128 + c], s);
        fold[t] = s;
    }
    __syncthreads();
    int i = blockIdx.x * blockDim.x + t;
    if (i >= n) return;
    float x0 = x[i * 6 + 1], x1 = x[i * 6 + 2], x2 = x[i * 6 + 3], x3 = x[i * 6 + 4];
#pragma unroll
    for (int h = 0; h < 4; h++) {
        float s = fmaf(x0, fold[h * 4 + 0], fmaf(x1, fold[h * 4 + 1],
                  fmaf(x2, fold[h * 4 + 2], x3 * fold[h * 4 + 3])));
        float d = fmaf(x0, fold[16 + h * 4 + 0], fmaf(x1, fold[16 + h * 4 + 1],
                  fmaf(x2, fold[16 + h * 4 + 2], x3 * fold[16 + h * 4 + 3])));
        ls[i * 4 + h] = s;
        ld[i * 4 + h] = d;
    }
}

// ---------------- layer-1 aggregate in input space: warp per dst node ----------------
__global__ void __launch_bounds__(256) k_gat1agg(
    const float* __restrict__ x, const float* __restrict__ ls,
    const float* __restrict__ ldv, const int* __restrict__ off,
    const int* __restrict__ srcs, float* __restrict__ agg) {
    int n = blockIdx.x * 8 + (threadIdx.x >> 5);
    int lane = threadIdx.x & 31;
    if (n >= NN) return;
    int start = off[n], end = off[n + 1];
    float4 ldq = *reinterpret_cast<const float4*>(ldv + n * 4);
    float m0 = -FLT_MAX, m1 = -FLT_MAX, m2 = -FLT_MAX, m3 = -FLT_MAX;
    for (int e = start + lane; e < end; e += 32) {
        int s = srcs[e];
        float4 lv = *reinterpret_cast<const float4*>(ls + s * 4);
        m0 = fmaxf(m0, lrelu02(lv.x + ldq.x));
        m1 = fmaxf(m1, lrelu02(lv.y + ldq.y));
        m2 = fmaxf(m2, lrelu02(lv.z + ldq.z));
        m3 = fmaxf(m3, lrelu02(lv.w + ldq.w));
    }
#pragma unroll
    for (int o = 16; o > 0; o >>= 1) {
        m0 = fmaxf(m0, __shfl_xor_sync(0xffffffffu, m0, o));
        m1 = fmaxf(m1, __shfl_xor_sync(0xffffffffu, m1, o));
        m2 = fmaxf(m2, __shfl_xor_sync(0xffffffffu, m2, o));
        m3 = fmaxf(m3, __shfl_xor_sync(0xffffffffu, m3, o));
    }
    float d0 = 0.f, d1 = 0.f, d2 = 0.f, d3 = 0.f;
    for (int e = start + lane; e < end; e += 32) {
        int s = srcs[e];
        float4 lv = *reinterpret_cast<const float4*>(ls + s * 4);
        d0 += expf(lrelu02(lv.x + ldq.x) - m0);
        d1 += expf(lrelu02(lv.y + ldq.y) - m1);
        d2 += expf(lrelu02(lv.z + ldq.z) - m2);
        d3 += expf(lrelu02(lv.w + ldq.w) - m3);
    }
#pragma unroll
    for (int o = 16; o > 0; o >>= 1) {
        d0 += __shfl_xor_sync(0xffffffffu, d0, o);
        d1 += __shfl_xor_sync(0xffffffffu, d1, o);
        d2 += __shfl_xor_sync(0xffffffffu, d2, o);
        d3 += __shfl_xor_sync(0xffffffffu, d3, o);
    }
    float rd0 = 0.25f / d0, rd1 = 0.25f / d1, rd2 = 0.25f / d2, rd3 = 0.25f / d3;
    float acc[16];
#pragma unroll
    for (int i = 0; i < 16; i++) acc[i] = 0.f;
    for (int e = start + lane; e < end; e += 32) {
        int s = srcs[e];
        float4 lv = *reinterpret_cast<const float4*>(ls + s * 4);
        float a0 = expf(lrelu02(lv.x + ldq.x) - m0) * rd0;
        float a1 = expf(lrelu02(lv.y + ldq.y) - m1) * rd1;
        float a2 = expf(lrelu02(lv.z + ldq.z) - m2) * rd2;
        float a3 = expf(lrelu02(lv.w + ldq.w) - m3) * rd3;
        const float* xr = x + (size_t)s * 6 + 1;
        float xv0 = xr[0], xv1 = xr[1], xv2 = xr[2], xv3 = xr[3];
        acc[0]  = fmaf(a0, xv0, acc[0]);  acc[1]  = fmaf(a0, xv1, acc[1]);
        acc[2]  = fmaf(a0, xv2, acc[2]);  acc[3]  = fmaf(a0, xv3, acc[3]);
        acc[4]  = fmaf(a1, xv0, acc[4]);  acc[5]  = fmaf(a1, xv1, acc[5]);
        acc[6]  = fmaf(a1, xv2, acc[6]);  acc[7]  = fmaf(a1, xv3, acc[7]);
        acc[8]  = fmaf(a2, xv0, acc[8]);  acc[9]  = fmaf(a2, xv1, acc[9]);
        acc[10] = fmaf(a2, xv2, acc[10]); acc[11] = fmaf(a2, xv3, acc[11]);
        acc[12] = fmaf(a3, xv0, acc[12]); acc[13] = fmaf(a3, xv1, acc[13]);
        acc[14] = fmaf(a3, xv2, acc[14]); acc[15] = fmaf(a3, xv3, acc[15]);
    }
#pragma unroll
    for (int i = 0; i < 16; i++) {
#pragma unroll
        for (int o = 16; o > 0; o >>= 1)
            acc[i] += __shfl_xor_sync(0xffffffffu, acc[i], o);
    }
    if (lane == 0) {
#pragma unroll
        for (int i = 0; i < 16; i++) agg[(size_t)n * 16 + i] = acc[i];
    }
}

// ---------------- layer-1 output projection + fused BN stats ----------------
__global__ void __launch_bounds__(128) k_out1(
    const float* __restrict__ agg, const float* __restrict__ W1,
    const float* __restrict__ b1, float* __restrict__ out, float* __restrict__ bnsum) {
    __shared__ float sA[256];
    int r0 = blockIdx.x * 16;
    int t = threadIdx.x;
    for (int i = t; i < 256; i += 128) sA[i] = agg[(size_t)r0 * 16 + i];
    __syncthreads();
    float w[16];
#pragma unroll
    for (int h = 0; h < 4; h++)
#pragma unroll
        for (int k = 0; k < 4; k++)
            w[h * 4 + k] = W1[k * 512 + h * 128 + t];
    float b = b1[t];
    float s = 0.f, q = 0.f;
#pragma unroll
    for (int r = 0; r < 16; r++) {
        float acc = b;
#pragma unroll
        for (int i = 0; i < 16; i++) acc = fmaf(sA[r * 16 + i], w[i], acc);
        out[(size_t)(r0 + r) * 128 + t] = acc;
        s += acc;
        q = fmaf(acc, acc, q);
    }
    atomicAdd(&bnsum[t], s);
    atomicAdd(&bnsum[128 + t], q);
}

// ---------------- fused GEMM (fmaf mainloop, ROWS rows/block, 2 cols/thread) ----------------
// PRE: 0 none; 1 BN+ELU+dropout; 2 BN+dropout. COEF: emit ls/ld. POST: 1 half; 2 LN+ReLU; 3 head.
template <int KK, int MM, int BD, int ROWS, int PRE, int POST, int COEF>
__global__ void __launch_bounds__(BD) k_gemm(
    const float* __restrict__ X, int ldx, int xcol0, const int* __restrict__ gidx,
    const float* __restrict__ W, const float* __restrict__ bias,
    float* __restrict__ Yf, __half* __restrict__ Yh,
    const float* __restrict__ bnsum, const float* __restrict__ bng,
    const float* __restrict__ bnbe, unsigned key0, unsigned key1,
    const float* __restrict__ lng, const float* __restrict__ lnb,
    const float* __restrict__ A3v, const float* __restrict__ ab3v,
    float* __restrict__ logits,
    const float* __restrict__ as_, const float* __restrict__ ad_,
    float* __restrict__ lsout, float* __restrict__ ldout) {
    static_assert(MM == 2 * BD, "MM must be 2*BD");
    extern __shared__ float xs[];
    __shared__ float red[ROWS][8];
    int r0 = blockIdx.x * ROWS;
    int tid = threadIdx.x;
    const float invN = 1.f / (float)NN;
    if (COEF) {
        for (int i = tid; i < ROWS * 8; i += BD) red[i >> 3][i & 7] = 0.f;
    }
    for (int i = tid; i < ROWS * KK; i += BD) {
        int r = i % ROWS, k = i / ROWS;
        int row = r0 + r;
        if (row >= NN) row = NN - 1;
        int srow = (gidx != nullptr) ? gidx[row] : row;
        float v = X[(size_t)srow * ldx + xcol0 + k];
        if (PRE > 0) {
            float mu = bnsum[k] * invN;
            float var = bnsum[KK + k] * invN - mu * mu;
            v = (v - mu) * rsqrtf(var + EPSV) * bng[k] + bnbe[k];
            if (PRE == 1) v = v > 0.f ? v : expm1f(v);
            unsigned bits = tf_xor(key0, key1, 0u, (unsigned)(srow * KK + k));
            v = (bits & 0x80000000u) ? 0.f : 2.f * v;
        }
        xs[k * ROWS + r] = v;
    }
    __syncthreads();
    int j0 = tid, j1 = tid + BD;
    float acc0[ROWS], acc1[ROWS];
    float b0 = bias ? bias[j0] : 0.f;
    float b1 = bias ? bias[j1] : 0.f;
#pragma unroll
    for (int r = 0; r < ROWS; r++) { acc0[r] = b0; acc1[r] = b1; }
#pragma unroll 4
    for (int k = 0; k < KK; k++) {
        float w0 = W[(size_t)k * MM + j0];
        float w1 = W[(size_t)k * MM + j1];
        const float4* xp = reinterpret_cast<const float4*>(xs + k * ROWS);
#pragma unroll
        for (int q = 0; q < ROWS / 4; q++) {
            float4 qv = xp[q];
            acc0[4 * q + 0] = fmaf(qv.x, w0, acc0[4 * q + 0]);
            acc0[4 * q + 1] = fmaf(qv.y, w0, acc0[4 * q + 1]);
            acc0[4 * q + 2] = fmaf(qv.z, w0, acc0[4 * q + 2]);
            acc0[4 * q + 3] = fmaf(qv.w, w0, acc0[4 * q + 3]);
            acc1[4 * q + 0] = fmaf(qv.x, w1, acc1[4 * q + 0]);
            acc1[4 * q + 1] = fmaf(qv.y, w1, acc1[4 * q + 1]);
            acc1[4 * q + 2] = fmaf(qv.z, w1, acc1[4 * q + 2]);
            acc1[4 * q + 3] = fmaf(qv.w, w1, acc1[4 * q + 3]);
        }
    }
    if (POST == 1) {
#pragma unroll
        for (int r = 0; r < ROWS; r++) {
            if (r0 + r < NN) {
                Yh[(size_t)(r0 + r) * MM + j0] = __float2half_rn(acc0[r]);
                Yh[(size_t)(r0 + r) * MM + j1] = __float2half_rn(acc1[r]);
            }
        }
    }
    if (COEF) {
        constexpr int C = MM / 4;
        int hd0 = j0 / C, hd1 = j1 / C;
        float as0 = as_[hd0 * C + (j0 % C)], ad0 = ad_[hd0 * C + (j0 % C)];
        float as1v = as_[hd1 * C + (j1 % C)], ad1v = ad_[hd1 * C + (j1 % C)];
        int lane = tid & 31;
#pragma unroll
        for (int r = 0; r < ROWS; r++) {
            float vs0 = acc0[r] * as0;
            float vd0 = acc0[r] * ad0;
            float vs1 = acc1[r] * as1v;
            float vd1 = acc1[r] * ad1v;
#pragma unroll
            for (int o = 16; o > 0; o >>= 1) {
                vs0 += __shfl_xor_sync(0xffffffffu, vs0, o);
                vd0 += __shfl_xor_sync(0xffffffffu, vd0, o);
                vs1 += __shfl_xor_sync(0xffffffffu, vs1, o);
                vd1 += __shfl_xor_sync(0xffffffffu, vd1, o);
            }
            if (lane == 0) {
                atomicAdd(&red[r][hd0], vs0);
                atomicAdd(&red[r][4 + hd0], vd0);
                atomicAdd(&red[r][hd1], vs1);
                atomicAdd(&red[r][4 + hd1], vd1);
            }
        }
        __syncthreads();
        if (tid < ROWS * 4) {
            int r = tid >> 2, hd = tid & 3;
            if (r0 + r < NN) {
                lsout[(r0 + r) * 4 + hd] = red[r][hd];
                ldout[(r0 + r) * 4 + hd] = red[r][4 + hd];
            }
        }
    }
    if (POST == 2) {
        __syncthreads();
#pragma unroll
        for (int r = 0; r < ROWS; r++) {
            xs[r * MM + j0] = acc0[r];
            xs[r * MM + j1] = acc1[r];
        }
        __syncthreads();
        int w = tid >> 5, lane = tid & 31;
        const int NW = BD / 32;
        const int VPL = MM / 32;
        for (int row = w; row < ROWS; row += NW) {
            float v[VPL];
            float s = 0.f, q = 0.f;
#pragma unroll
            for (int i = 0; i < VPL; i++) {
                v[i] = xs[row * MM + lane + 32 * i];
                s += v[i]; q = fmaf(v[i], v[i], q);
            }
#pragma unroll
            for (int o = 16; o > 0; o >>= 1) {
                s += __shfl_xor_sync(0xffffffffu, s, o);
                q += __shfl_xor_sync(0xffffffffu, q, o);
            }
            float mu = s / (float)MM;
            float var = q / (float)MM - mu * mu;
            float rs = rsqrtf(var + EPSV);
            if (r0 + row < NN) {
#pragma unroll
                for (int i = 0; i < VPL; i++) {
                    int c = lane + 32 * i;
                    float y = (v[i] - mu) * rs * lng[c] + lnb[c];
                    Yf[(size_t)(r0 + row) * MM + c] = fmaxf(y, 0.f);
                }
            }
        }
    } else if (POST == 3) {
        __syncthreads();
#pragma unroll
        for (int r = 0; r < ROWS; r++) {
            xs[r * MM + j0] = acc0[r];
            xs[r * MM + j1] = acc1[r];
        }
        __syncwarp();
        int lane = tid & 31;
        float a30 = A3v[lane], a31 = A3v[lane + 32];
        float bb = ab3v[0];
        for (int row = 0; row < ROWS; row++) {
            float v0 = xs[row * MM + lane];
            float v1 = xs[row * MM + lane + 32];
            float s = v0 + v1;
            float q = fmaf(v0, v0, v1 * v1);
#pragma unroll
            for (int o = 16; o > 0; o >>= 1) {
                s += __shfl_xor_sync(0xffffffffu, s, o);
                q += __shfl_xor_sync(0xffffffffu, q, o);
            }
            float mu = s / 64.f;
            float var = q / 64.f - mu * mu;
            float rs = rsqrtf(var + EPSV);
            float y0 = fmaxf((v0 - mu) * rs * lng[lane] + lnb[lane], 0.f);
            float y1 = fmaxf((v1 - mu) * rs * lng[lane + 32] + lnb[lane + 32], 0.f);
            float t = fmaf(y0, a30, y1 * a31);
#pragma unroll
            for (int o = 16; o > 0; o >>= 1) t += __shfl_xor_sync(0xffffffffu, t, o);
            if (lane == 0 && r0 + row < NN) logits[r0 + row] = tanhf(t + bb);
        }
    }
}

// ---------------- fused GAT softmax + aggregate: one node per block ----------------
template <int C>
__global__ void __launch_bounds__(2 * C) k_gat(
    const __half* __restrict__ h, const float* __restrict__ ls,
    const float* __restrict__ ldv, const int* __restrict__ off,
    const int* __restrict__ srcs, const float* __restrict__ bias,
    float* __restrict__ out) {
    constexpr int CHUNK = 64;
    __shared__ float s_alpha[CHUNK * 4];
    __shared__ int s_srcs[CHUNK];
    __shared__ float s_out[4 * C];
    int n = blockIdx.x;
    int t = threadIdx.x;
    int lane = t & 31;
    int start = off[n], end = off[n + 1];
    float m0 = -FLT_MAX, m1 = -FLT_MAX, m2 = -FLT_MAX, m3 = -FLT_MAX;
    float rd0 = 0.f, rd1 = 0.f, rd2 = 0.f, rd3 = 0.f;
    float ldx = 0.f, ldy = 0.f, ldz = 0.f, ldw = 0.f;
    if (t < 32) {
        float4 ldq = *reinterpret_cast<const float4*>(ldv + n * 4);
        ldx = ldq.x; ldy = ldq.y; ldz = ldq.z; ldw = ldq.w;
        for (int e = start + lane; e < end; e += 32) {
            int s = srcs[e];
            float4 lv = *reinterpret_cast<const float4*>(ls + s * 4);
            m0 = fmaxf(m0, lrelu02(lv.x + ldx));
            m1 = fmaxf(m1, lrelu02(lv.y + ldy));
            m2 = fmaxf(m2, lrelu02(lv.z + ldz));
            m3 = fmaxf(m3, lrelu02(lv.w + ldw));
        }
#pragma unroll
        for (int o = 16; o > 0; o >>= 1) {
            m0 = fmaxf(m0, __shfl_xor_sync(0xffffffffu, m0, o));
            m1 = fmaxf(m1, __shfl_xor_sync(0xffffffffu, m1, o));
            m2 = fmaxf(m2, __shfl_xor_sync(0xffffffffu, m2, o));
            m3 = fmaxf(m3, __shfl_xor_sync(0xffffffffu, m3, o));
        }
        float d0 = 0.f, d1 = 0.f, d2 = 0.f, d3 = 0.f;
        for (int e = start + lane; e < end; e += 32) {
            int s = srcs[e];
            float4 lv = *reinterpret_cast<const float4*>(ls + s * 4);
            d0 += expf(lrelu02(lv.x + ldx) - m0);
            d1 += expf(lrelu02(lv.y + ldy) - m1);
            d2 += expf(lrelu02(lv.z + ldz) - m2);
            d3 += expf(lrelu02(lv.w + ldw) - m3);
        }
#pragma unroll
        for (int o = 16; o > 0; o >>= 1) {
            d0 += __shfl_xor_sync(0xffffffffu, d0, o);
            d1 += __shfl_xor_sync(0xffffffffu, d1, o);
            d2 += __shfl_xor_sync(0xffffffffu, d2, o);
            d3 += __shfl_xor_sync(0xffffffffu, d3, o);
        }
        rd0 = 0.25f / d0; rd1 = 0.25f / d1; rd2 = 0.25f / d2; rd3 = 0.25f / d3;
    }
    int head = t / (C / 2);
    int pair = t % (C / 2);
    float accx = 0.f, accy = 0.f;
    for (int cs = start; cs < end; cs += CHUNK) {
        int ce = min(cs + CHUNK, end);
        if (t < 32) {
            for (int e = cs + lane; e < ce; e += 32) {
                int s = srcs[e];
                float4 lv = *reinterpret_cast<const float4*>(ls + s * 4);
                int i = e - cs;
                s_srcs[i] = s;
                s_alpha[i * 4 + 0] = expf(lrelu02(lv.x + ldx) - m0) * rd0;
                s_alpha[i * 4 + 1] = expf(lrelu02(lv.y + ldy) - m1) * rd1;
                s_alpha[i * 4 + 2] = expf(lrelu02(lv.z + ldz) - m2) * rd2;
                s_alpha[i * 4 + 3] = expf(lrelu02(lv.w + ldw) - m3) * rd3;
            }
        }
        __syncthreads();
        int cnt = ce - cs;
        int i = 0;
        for (; i + 2 <= cnt; i += 2) {
            int s0 = s_srcs[i], s1 = s_srcs[i + 1];
            float a0 = s_alpha[i * 4 + head];
            float a1 = s_alpha[(i + 1) * 4 + head];
            __half2 v0 = *reinterpret_cast<const __half2*>(h + ((size_t)s0 * 4 + head) * C + 2 * pair);
            __half2 v1 = *reinterpret_cast<const __half2*>(h + ((size_t)s1 * 4 + head) * C + 2 * pair);
            float2 f0 = __half22float2(v0), f1 = __half22float2(v1);
            accx = fmaf(f0.x, a0, fmaf(f1.x, a1, accx));
            accy = fmaf(f0.y, a0, fmaf(f1.y, a1, accy));
        }
        if (i < cnt) {
            int s0 = s_srcs[i];
            float a0 = s_alpha[i * 4 + head];
            float2 f0 = __half22float2(
                *reinterpret_cast<const __half2*>(h + ((size_t)s0 * 4 + head) * C + 2 * pair));
            accx = fmaf(f0.x, a0, accx);
            accy = fmaf(f0.y, a0, accy);
        }
        __syncthreads();
    }
    s_out[head * C + 2 * pair] = accx;
    s_out[head * C + 2 * pair + 1] = accy;
    __syncthreads();
    if (t < C) {
        float v = (s_out[t] + s_out[C + t]) + (s_out[2 * C + t] + s_out[3 * C + t]) + bias[t];
        out[(size_t)n * C + t] = v;
    }
}

// ---------------- BN stats ----------------
__global__ void k_bn_stats(const float* __restrict__ x, int N, int C, float* __restrict__ sums) {
    int t = threadIdx.x;
    int r0 = blockIdx.x * 256;
    int r1 = min(r0 + 256, N);
    float s = 0.f, q = 0.f;
    for (int r = r0; r < r1; r++) {
        float v = x[(size_t)r * C + t];
        s += v; q = fmaf(v, v, q);
    }
    atomicAdd(&sums[t], s);
    atomicAdd(&sums[C + t], q);
}

// ---------------- softmax ----------------
__global__ void k_smax_part(const float* __restrict__ lg, int n, float* __restrict__ part) {
    __shared__ float sm[256], ss[256];
    float m = -FLT_MAX, s = 0.f;
    for (int i = blockIdx.x * 256 + threadIdx.x; i < n; i += 128 * 256) {
        float v = lg[i];
        float nm = fmaxf(m, v);
        s = s * expf(m - nm) + expf(v - nm);
        m = nm;
    }
    sm[threadIdx.x] = m; ss[threadIdx.x] = s;
    __syncthreads();
    for (int o = 128; o > 0; o >>= 1) {
        if (threadIdx.x < o) {
            float m2 = sm[threadIdx.x + o], s2 = ss[threadIdx.x + o];
            float nm = fmaxf(sm[threadIdx.x], m2);
            ss[threadIdx.x] = ss[threadIdx.x] * expf(sm[threadIdx.x] - nm) + s2 * expf(m2 - nm);
            sm[threadIdx.x] = nm;
        }
        __syncthreads();
    }
    if (threadIdx.x == 0) { part[blockIdx.x] = sm[0]; part[128 + blockIdx.x] = ss[0]; }
}
__global__ void k_smax_fin(const float* __restrict__ lg, int n,
                           const float* __restrict__ part, float* __restrict__ out) {
    __shared__ float sm[128], ss[128];
    __shared__ float fM, fS;
    int t = threadIdx.x;
    if (t < 128) { sm[t] = part[t]; ss[t] = part[128 + t]; }
    __syncthreads();
    for (int o = 64; o > 0; o >>= 1) {
        if (t < o) {
            float m2 = sm[t + o], s2 = ss[t + o];
            float nm = fmaxf(sm[t], m2);
            ss[t] = ss[t] * expf(sm[t] - nm) + s2 * expf(m2 - nm);
            sm[t] = nm;
        }
        __syncthreads();
    }
    if (t == 0) { fM = sm[0]; fS = ss[0]; }
    __syncthreads();
    float M = fM, S = fS;
    for (int i = t; i < n; i += 1024) {
        float l = lg[i];
        out[i] = l;
        out[n + i] = expf(l - M) / S;
    }
}

// ---------------- launch ----------------
extern "C" void kernel_launch(void* const* d_in, const int* in_sizes, int n_in,
                              void* d_out, int out_size) {
    const float* x   = (const float*)d_in[0];
    const int* ei    = (const int*)d_in[1];
    int E = in_sizes[1] / 2;
    const int* esrc = ei;
    const int* edst = ei + E;
    const float* W1  = (const float*)d_in[2];
    const float* as1 = (const float*)d_in[3];
    const float* ad1 = (const float*)d_in[4];
    const float* b1  = (const float*)d_in[5];
    const float* g1  = (const float*)d_in[6];
    const float* be1 = (const float*)d_in[7];
    const float* W2  = (const float*)d_in[8];
    const float* as2 = (const float*)d_in[9];
    const float* ad2 = (const float*)d_in[10];
    const float* b2  = (const float*)d_in[11];
    const float* g2  = (const float*)d_in[12];
    const float* be2 = (const float*)d_in[13];
    const float* W3  = (const float*)d_in[14];
    const float* as3 = (const float*)d_in[15];
    const float* ad3 = (const float*)d_in[16];
    const float* b3  = (const float*)d_in[17];
    const float* g3  = (const float*)d_in[18];
    const float* be3 = (const float*)d_in[19];
    const float* A1  = (const float*)d_in[20];
    const float* ab1 = (const float*)d_in[21];
    const float* l1g = (const float*)d_in[22];
    const float* l1b = (const float*)d_in[23];
    const float* A2  = (const float*)d_in[24];
    const float* ab2 = (const float*)d_in[25];
    const float* l2g = (const float*)d_in[26];
    const float* l2b = (const float*)d_in[27];
    const float* A3  = (const float*)d_in[28];
    const float* ab3 = (const float*)d_in[29];

    __half* h;
    float *io0, *io1, *ls, *ld, *logits, *bn, *part;
    int *deg, *off, *cur, *srcs, *bsum;
    cudaGetSymbolAddress((void**)&h, g_h);
    cudaGetSymbolAddress((void**)&io0, g_io0);
    cudaGetSymbolAddress((void**)&io1, g_io1);
    cudaGetSymbolAddress((void**)&ls, g_ls);
    cudaGetSymbolAddress((void**)&ld, g_ld);
    cudaGetSymbolAddress((void**)&logits, g_logits);
    cudaGetSymbolAddress((void**)&bn, g_bn);
    cudaGetSymbolAddress((void**)&part, g_part);
    cudaGetSymbolAddress((void**)&deg, g_deg);
    cudaGetSymbolAddress((void**)&off, g_off);
    cudaGetSymbolAddress((void**)&cur, g_cur);
    cudaGetSymbolAddress((void**)&srcs, g_srcs);
    cudaGetSymbolAddress((void**)&bsum, g_bsum);

    unsigned dk[3][2];
    for (unsigned i = 0; i < 3; i++) tf_host(0u, 42u, 0u, i, &dk[i][0], &dk[i][1]);

    const int nb = (NN + 255) / 256;  // 196
    const int NG = NN / 16;           // 3125
    const int NG32 = (NN + 31) / 32;  // 1563

    // ---- CSR build ----
    k_init<<<nb, 256>>>(deg, bn, NN);
    k_count<<<(E + 255) / 256, 256>>>(edst, E, deg);
    k_scan1<<<nb, 256>>>(deg, off, bsum, NN);
    k_scan2<<<1, 256>>>(bsum, nb, off + NN);
    k_scan3<0><<<nb, 256>>>(off, bsum, cur, NN);
    k_scatter<<<(E + NN + 255) / 256, 256>>>(esrc, edst, E, NN, cur, srcs);

    // ---- layer 1: aggregate-then-project ----
    k_coef1<<<nb, 256>>>(x, W1, as1, ad1, ls, ld, NN);
    k_gat1agg<<<(NN + 7) / 8, 256>>>(x, ls, ld, off, srcs, io1);
    k_out1<<<NG, 128>>>(io1, W1, b1, io0, bn);

    // ---- layer 2: BN1+ELU+drop0 fused; 128 -> 4x64 + coef (ROWS=32) ----
    k_gemm<128, 256, 128, 32, 1, 1, 1><<<NG32, 128, 32 * 128 * 4>>>(
        io0, 128, 0, nullptr, W2, nullptr, nullptr, h,
        bn, g1, be1, dk[0][0], dk[0][1], nullptr, nullptr, nullptr, nullptr, nullptr,
        as2, ad2, ls, ld);
    k_gat<64><<<NN, 128>>>(h, ls, ld, off, srcs, b2, io1);
    k_bn_stats<<<nb, 64>>>(io1, NN, 64, bn + 256);

    // ---- layer 3: BN2+ELU+drop1 fused; 64 -> 4x32 + coef ----
    k_gemm<64, 128, 64, 16, 1, 1, 1><<<NG, 64, 16 * 64 * 4>>>(
        io1, 64, 0, nullptr, W3, nullptr, nullptr, h,
        bn + 256, g2, be2, dk[1][0], dk[1][1], nullptr, nullptr, nullptr, nullptr, nullptr,
        as3, ad3, ls, ld);
    k_gat<32><<<NN, 64>>>(h, ls, ld, off, srcs, b3, io0);
    k_bn_stats<<<nb, 32>>>(io0, NN, 32, bn + 384);

    // ---- selection ----
    k_scan1_cond<<<nb, 256>>>(x, off, bsum, NN);
    k_scan2<<<1, 256>>>(bsum, nb, nullptr);
    k_scan3<1><<<nb, 256>>>(off, bsum, cur, NN);
    k_idx_scatter<<<nb, 256>>>(x, off, cur, NN);

    // ---- MLP head ----
    k_gemm<32, 128, 64, 16, 2, 2, 0><<<NG, 64, 16 * 128 * 4>>>(
        io0, 32, 0, cur, A1, ab1, io1, nullptr,
        bn + 384, g3, be3, dk[2][0], dk[2][1], l1g, l1b, nullptr, nullptr, nullptr,
        nullptr, nullptr, nullptr, nullptr);
    k_gemm<128, 64, 32, 16, 0, 3, 0><<<NG, 32, 16 * 128 * 4>>>(
        io1, 128, 0, nullptr, A2, ab2, nullptr, nullptr,
        nullptr, nullptr, nullptr, 0u, 0u, l2g, l2b, A3, ab3, logits,
        nullptr, nullptr, nullptr, nullptr);

    // ---- softmax ----
    k_smax_part<<<128, 256>>>(logits, NN, part);
    k_smax_fin<<<1, 1024>>>(logits, NN, part, (float*)d_out);
}

// round 13
// speedup vs baseline: 1.0864x; 1.0864x over previous
#include <cuda_runtime.h>
#include <cuda_fp16.h>
#include <math.h>
#include <float.h>
#include <stdint.h>

#define NN 50000
#define EE 400000
#define EPSV 1e-5f

// ---------------- scratch ----------------
__device__ __half g_h[(size_t)NN * 512];
__device__ float g_io0[(size_t)NN * 128];
__device__ float g_io1[(size_t)NN * 128];   // also reused as agg[NN][16]
__device__ float g_ls[NN * 4];
__device__ float g_ld[NN * 4];
__device__ float g_logits[NN];
__device__ float g_bn[448];
__device__ float g_part[256];
__device__ int   g_deg[NN];
__device__ int   g_off[NN + 1];
__device__ int   g_cur[NN];
__device__ int   g_srcs[EE + NN];
__device__ int   g_bsum[256];

// ---------------- threefry2x32 (partitionable xor bits) ----------------
__device__ __forceinline__ unsigned rotl32d(unsigned v, int r) {
    return __funnelshift_l(v, v, r);
}
__device__ __forceinline__ unsigned tf_xor(unsigned k0, unsigned k1, unsigned x0, unsigned x1) {
    unsigned k2 = k0 ^ k1 ^ 0x1BD11BDAu;
    x0 += k0; x1 += k1;
#define TF_R(r) { x0 += x1; x1 = rotl32d(x1, r); x1 ^= x0; }
    TF_R(13) TF_R(15) TF_R(26) TF_R(6)   x0 += k1; x1 += k2 + 1u;
    TF_R(17) TF_R(29) TF_R(16) TF_R(24)  x0 += k2; x1 += k0 + 2u;
    TF_R(13) TF_R(15) TF_R(26) TF_R(6)   x0 += k0; x1 += k1 + 3u;
    TF_R(17) TF_R(29) TF_R(16) TF_R(24)  x0 += k1; x1 += k2 + 4u;
    TF_R(13) TF_R(15) TF_R(26) TF_R(6)   x0 += k2; x1 += k0 + 5u;
#undef TF_R
    return x0 ^ x1;
}
static inline unsigned rotl32h(unsigned v, int r) { return (v << r) | (v >> (32 - r)); }
static void tf_host(unsigned k0, unsigned k1, unsigned x0, unsigned x1,
                    unsigned* o0, unsigned* o1) {
    unsigned k2 = k0 ^ k1 ^ 0x1BD11BDAu;
    x0 += k0; x1 += k1;
#define TF_RH(r) { x0 += x1; x1 = rotl32h(x1, r); x1 ^= x0; }
    TF_RH(13) TF_RH(15) TF_RH(26) TF_RH(6)   x0 += k1; x1 += k2 + 1u;
    TF_RH(17) TF_RH(29) TF_RH(16) TF_RH(24)  x0 += k2; x1 += k0 + 2u;
    TF_RH(13) TF_RH(15) TF_RH(26) TF_RH(6)   x0 += k0; x1 += k1 + 3u;
    TF_RH(17) TF_RH(29) TF_RH(16) TF_RH(24)  x0 += k1; x1 += k2 + 4u;
    TF_RH(13) TF_RH(15) TF_RH(26) TF_RH(6)   x0 += k2; x1 += k0 + 5u;
#undef TF_RH
    *o0 = x0; *o1 = x1;
}

__global__ void k_count(const int* __restrict__ dst, int e, int* deg) {
    int i = blockIdx.x * blockDim.x + threadIdx.x;
    if (i < e) atomicAdd(&deg[dst[i]], 1);
}

// ---------------- 3-stage scan ----------------
__global__ void k_scan1(const int* __restrict__ in, int* __restrict__ out,
                        int* __restrict__ bsum, int n) {
    __shared__ int sh[256];
    int i = blockIdx.x * 256 + threadIdx.x;
    int t = threadIdx.x;
    int v = (i < n) ? in[i] : 0;
    sh[t] = v;
    __syncthreads();
#pragma unroll
    for (int o = 1; o < 256; o <<= 1) {
        int add = (t >= o) ? sh[t - o] : 0;
        __syncthreads();
        sh[t] += add;
        __syncthreads();
    }
    if (i < n) out[i] = sh[t] - v;
    if (t == 255) bsum[blockIdx.x] = sh[255];
}
__global__ void k_scan1_cond(const float* __restrict__ x, int* __restrict__ out,
                             int* __restrict__ bsum, int n) {
    __shared__ int sh[256];
    int i = blockIdx.x * 256 + threadIdx.x;
    int t = threadIdx.x;
    int v = 0;
    if (i < n) v = (x[i * 6 + 2] == 1.0f && x[i * 6 + 5] == 0.0f) ? 1 : 0;
    sh[t] = v;
    __syncthreads();
#pragma unroll
    for (int o = 1; o < 256; o <<= 1) {
        int add = (t >= o) ? sh[t - o] : 0;
        __syncthreads();
        sh[t] += add;
        __syncthreads();
    }
    if (i < n) out[i] = sh[t] - v;
    if (t == 255) bsum[blockIdx.x] = sh[255];
}
__global__ void k_scan2(int* __restrict__ bsum, int nb, int* __restrict__ total) {
    __shared__ int sh[256];
    int t = threadIdx.x;
    int v = (t < nb) ? bsum[t] : 0;
    sh[t] = v;
    __syncthreads();
#pragma unroll
    for (int o = 1; o < 256; o <<= 1) {
        int add = (t >= o) ? sh[t - o] : 0;
        __syncthreads();
        sh[t] += add;
        __syncthreads();
    }
    if (t < nb) bsum[t] = sh[t] - v;
    if (t == 0 && total) *total = sh[255];
}
template <int MODE>
__global__ void k_scan3(int* __restrict__ out, const int* __restrict__ bsum,
                        int* __restrict__ cur, int n) {
    int i = blockIdx.x * 256 + threadIdx.x;
    if (i < n) {
        int v = out[i] + bsum[blockIdx.x];
        out[i] = v;
        cur[i] = MODE ? 0 : v;
    }
}
__global__ void k_scatter(const int* __restrict__ src, const int* __restrict__ dst,
                          int e, int n, int* cur, int* __restrict__ outsrc) {
    int i = blockIdx.x * blockDim.x + threadIdx.x;
    if (i < e) {
        int p = atomicAdd(&cur[dst[i]], 1);
        outsrc[p] = src[i];
    } else if (i < e + n) {
        int nd = i - e;
        int p = atomicAdd(&cur[nd], 1);
        outsrc[p] = nd;
    }
}
__global__ void k_idx_scatter(const float* __restrict__ x, const int* __restrict__ pos,
                              int* __restrict__ idx, int n) {
    int i = blockIdx.x * blockDim.x + threadIdx.x;
    if (i < n && x[i * 6 + 2] == 1.0f && x[i * 6 + 5] == 0.0f) idx[pos[i]] = i;
}

__device__ __forceinline__ float lrelu02(float v) { return v > 0.f ? v : 0.2f * v; }

// ---------------- layer-1 coef with in-block fold + global init fused ----------------
__global__ void k_coef1(const float* __restrict__ x, const float* __restrict__ W1,
                        const float* __restrict__ as1, const float* __restrict__ ad1,
                        float* __restrict__ ls, float* __restrict__ ld, int n,
                        int* __restrict__ deg, float* __restrict__ bnz) {
    __shared__ float fold[32];
    int t = threadIdx.x;
    int i = blockIdx.x * blockDim.x + t;
    if (i < n) deg[i] = 1;          // fused k_init
    if (i < 448) bnz[i] = 0.f;
    if (t < 32) {
        int h = (t & 15) >> 2, k = t & 3;
        const float* a = (t < 16) ? as1 : ad1;
        float s = 0.f;
        for (int c = 0; c < 128; c++)
            s = fmaf(W1[k * 512 + h * 128 + c], a[h * 128 + c], s);
        fold[t] = s;
    }
    __syncthreads();
    if (i >= n) return;
    float x0 = x[i * 6 + 1], x1 = x[i * 6 + 2], x2 = x[i * 6 + 3], x3 = x[i * 6 + 4];
#pragma unroll
    for (int h = 0; h < 4; h++) {
        float s = fmaf(x0, fold[h * 4 + 0], fmaf(x1, fold[h * 4 + 1],
                  fmaf(x2, fold[h * 4 + 2], x3 * fold[h * 4 + 3])));
        float d = fmaf(x0, fold[16 + h * 4 + 0], fmaf(x1, fold[16 + h * 4 + 1],
                  fmaf(x2, fold[16 + h * 4 + 2], x3 * fold[16 + h * 4 + 3])));
        ls[i * 4 + h] = s;
        ld[i * 4 + h] = d;
    }
}

// ---------------- layer-1 aggregate in input space: warp per dst node ----------------
__global__ void __launch_bounds__(256) k_gat1agg(
    const float* __restrict__ x, const float* __restrict__ ls,
    const float* __restrict__ ldv, const int* __restrict__ off,
    const int* __restrict__ srcs, float* __restrict__ agg) {
    int n = blockIdx.x * 8 + (threadIdx.x >> 5);
    int lane = threadIdx.x & 31;
    if (n >= NN) return;
    int start = off[n], end = off[n + 1];
    float4 ldq = *reinterpret_cast<const float4*>(ldv + n * 4);
    float m0 = -FLT_MAX, m1 = -FLT_MAX, m2 = -FLT_MAX, m3 = -FLT_MAX;
    for (int e = start + lane; e < end; e += 32) {
        int s = srcs[e];
        float4 lv = *reinterpret_cast<const float4*>(ls + s * 4);
        m0 = fmaxf(m0, lrelu02(lv.x + ldq.x));
        m1 = fmaxf(m1, lrelu02(lv.y + ldq.y));
        m2 = fmaxf(m2, lrelu02(lv.z + ldq.z));
        m3 = fmaxf(m3, lrelu02(lv.w + ldq.w));
    }
#pragma unroll
    for (int o = 16; o > 0; o >>= 1) {
        m0 = fmaxf(m0, __shfl_xor_sync(0xffffffffu, m0, o));
        m1 = fmaxf(m1, __shfl_xor_sync(0xffffffffu, m1, o));
        m2 = fmaxf(m2, __shfl_xor_sync(0xffffffffu, m2, o));
        m3 = fmaxf(m3, __shfl_xor_sync(0xffffffffu, m3, o));
    }
    float d0 = 0.f, d1 = 0.f, d2 = 0.f, d3 = 0.f;
    for (int e = start + lane; e < end; e += 32) {
        int s = srcs[e];
        float4 lv = *reinterpret_cast<const float4*>(ls + s * 4);
        d0 += expf(lrelu02(lv.x + ldq.x) - m0);
        d1 += expf(lrelu02(lv.y + ldq.y) - m1);
        d2 += expf(lrelu02(lv.z + ldq.z) - m2);
        d3 += expf(lrelu02(lv.w + ldq.w) - m3);
    }
#pragma unroll
    for (int o = 16; o > 0; o >>= 1) {
        d0 += __shfl_xor_sync(0xffffffffu, d0, o);
        d1 += __shfl_xor_sync(0xffffffffu, d1, o);
        d2 += __shfl_xor_sync(0xffffffffu, d2, o);
        d3 += __shfl_xor_sync(0xffffffffu, d3, o);
    }
    float rd0 = 0.25f / d0, rd1 = 0.25f / d1, rd2 = 0.25f / d2, rd3 = 0.25f / d3;
    float acc[16];
#pragma unroll
    for (int i = 0; i < 16; i++) acc[i] = 0.f;
    for (int e = start + lane; e < end; e += 32) {
        int s = srcs[e];
        float4 lv = *reinterpret_cast<const float4*>(ls + s * 4);
        float a0 = expf(lrelu02(lv.x + ldq.x) - m0) * rd0;
        float a1 = expf(lrelu02(lv.y + ldq.y) - m1) * rd1;
        float a2 = expf(lrelu02(lv.z + ldq.z) - m2) * rd2;
        float a3 = expf(lrelu02(lv.w + ldq.w) - m3) * rd3;
        const float* xr = x + (size_t)s * 6 + 1;
        float xv0 = xr[0], xv1 = xr[1], xv2 = xr[2], xv3 = xr[3];
        acc[0]  = fmaf(a0, xv0, acc[0]);  acc[1]  = fmaf(a0, xv1, acc[1]);
        acc[2]  = fmaf(a0, xv2, acc[2]);  acc[3]  = fmaf(a0, xv3, acc[3]);
        acc[4]  = fmaf(a1, xv0, acc[4]);  acc[5]  = fmaf(a1, xv1, acc[5]);
        acc[6]  = fmaf(a1, xv2, acc[6]);  acc[7]  = fmaf(a1, xv3, acc[7]);
        acc[8]  = fmaf(a2, xv0, acc[8]);  acc[9]  = fmaf(a2, xv1, acc[9]);
        acc[10] = fmaf(a2, xv2, acc[10]); acc[11] = fmaf(a2, xv3, acc[11]);
        acc[12] = fmaf(a3, xv0, acc[12]); acc[13] = fmaf(a3, xv1, acc[13]);
        acc[14] = fmaf(a3, xv2, acc[14]); acc[15] = fmaf(a3, xv3, acc[15]);
    }
#pragma unroll
    for (int i = 0; i < 16; i++) {
#pragma unroll
        for (int o = 16; o > 0; o >>= 1)
            acc[i] += __shfl_xor_sync(0xffffffffu, acc[i], o);
    }
    if (lane == 0) {
#pragma unroll
        for (int i = 0; i < 16; i++) agg[(size_t)n * 16 + i] = acc[i];
    }
}

// ---------------- layer-1 output projection + fused BN stats ----------------
__global__ void __launch_bounds__(128) k_out1(
    const float* __restrict__ agg, const float* __restrict__ W1,
    const float* __restrict__ b1, float* __restrict__ out, float* __restrict__ bnsum) {
    __shared__ float sA[256];
    int r0 = blockIdx.x * 16;
    int t = threadIdx.x;
    for (int i = t; i < 256; i += 128) sA[i] = agg[(size_t)r0 * 16 + i];
    __syncthreads();
    float w[16];
#pragma unroll
    for (int h = 0; h < 4; h++)
#pragma unroll
        for (int k = 0; k < 4; k++)
            w[h * 4 + k] = W1[k * 512 + h * 128 + t];
    float b = b1[t];
    float s = 0.f, q = 0.f;
#pragma unroll
    for (int r = 0; r < 16; r++) {
        float acc = b;
#pragma unroll
        for (int i = 0; i < 16; i++) acc = fmaf(sA[r * 16 + i], w[i], acc);
        out[(size_t)(r0 + r) * 128 + t] = acc;
        s += acc;
        q = fmaf(acc, acc, q);
    }
    atomicAdd(&bnsum[t], s);
    atomicAdd(&bnsum[128 + t], q);
}

// ---------------- fused GEMM (R10 config: fmaf mainloop, 16 rows, 2 cols/thread) ----------------
// PRE: 0 none; 1 BN+ELU+dropout; 2 BN+dropout. COEF: emit ls/ld. POST: 1 half.
template <int KK, int MM, int BD, int PRE, int POST, int COEF>
__global__ void __launch_bounds__(BD) k_gemm(
    const float* __restrict__ X, int ldx, int xcol0, const int* __restrict__ gidx,
    const float* __restrict__ W, const float* __restrict__ bias,
    float* __restrict__ Yf, __half* __restrict__ Yh,
    const float* __restrict__ bnsum, const float* __restrict__ bng,
    const float* __restrict__ bnbe, unsigned key0, unsigned key1,
    const float* __restrict__ as_, const float* __restrict__ ad_,
    float* __restrict__ lsout, float* __restrict__ ldout) {
    static_assert(MM == 2 * BD, "MM must be 2*BD");
    extern __shared__ float xs[];
    __shared__ float red[16][8];
    int r0 = blockIdx.x * 16;
    int tid = threadIdx.x;
    const float invN = 1.f / (float)NN;
    if (COEF) {
        for (int i = tid; i < 128; i += BD) red[i >> 3][i & 7] = 0.f;
    }
    for (int i = tid; i < 16 * KK; i += BD) {
        int r = i & 15, k = i >> 4;
        int row = r0 + r;
        int srow = (gidx != nullptr) ? gidx[row] : row;
        float v = X[(size_t)srow * ldx + xcol0 + k];
        if (PRE > 0) {
            float mu = bnsum[k] * invN;
            float var = bnsum[KK + k] * invN - mu * mu;
            v = (v - mu) * rsqrtf(var + EPSV) * bng[k] + bnbe[k];
            if (PRE == 1) v = v > 0.f ? v : expm1f(v);
            unsigned bits = tf_xor(key0, key1, 0u, (unsigned)(srow * KK + k));
            v = (bits & 0x80000000u) ? 0.f : 2.f * v;
        }
        xs[k * 16 + r] = v;
    }
    __syncthreads();
    int j0 = tid, j1 = tid + BD;
    float acc0[16], acc1[16];
    float b0 = bias ? bias[j0] : 0.f;
    float b1 = bias ? bias[j1] : 0.f;
#pragma unroll
    for (int r = 0; r < 16; r++) { acc0[r] = b0; acc1[r] = b1; }
#pragma unroll 4
    for (int k = 0; k < KK; k++) {
        float w0 = W[(size_t)k * MM + j0];
        float w1 = W[(size_t)k * MM + j1];
        const float4* xp = reinterpret_cast<const float4*>(xs + k * 16);
        float4 q0 = xp[0], q1 = xp[1], q2 = xp[2], q3 = xp[3];
        float xv[16] = {q0.x, q0.y, q0.z, q0.w, q1.x, q1.y, q1.z, q1.w,
                        q2.x, q2.y, q2.z, q2.w, q3.x, q3.y, q3.z, q3.w};
#pragma unroll
        for (int r = 0; r < 16; r++) {
            acc0[r] = fmaf(xv[r], w0, acc0[r]);
            acc1[r] = fmaf(xv[r], w1, acc1[r]);
        }
    }
    if (POST == 1) {
#pragma unroll
        for (int r = 0; r < 16; r++) {
            Yh[(size_t)(r0 + r) * MM + j0] = __float2half_rn(acc0[r]);
            Yh[(size_t)(r0 + r) * MM + j1] = __float2half_rn(acc1[r]);
        }
    }
    if (COEF) {
        constexpr int C = MM / 4;
        int hd0 = j0 / C, hd1 = j1 / C;
        float as0 = as_[hd0 * C + (j0 % C)], ad0 = ad_[hd0 * C + (j0 % C)];
        float as1v = as_[hd1 * C + (j1 % C)], ad1v = ad_[hd1 * C + (j1 % C)];
        int lane = tid & 31;
#pragma unroll
        for (int r = 0; r < 16; r++) {
            float vs0 = acc0[r] * as0;
            float vd0 = acc0[r] * ad0;
            float vs1 = acc1[r] * as1v;
            float vd1 = acc1[r] * ad1v;
#pragma unroll
            for (int o = 16; o > 0; o >>= 1) {
                vs0 += __shfl_xor_sync(0xffffffffu, vs0, o);
                vd0 += __shfl_xor_sync(0xffffffffu, vd0, o);
                vs1 += __shfl_xor_sync(0xffffffffu, vs1, o);
                vd1 += __shfl_xor_sync(0xffffffffu, vd1, o);
            }
            if (lane == 0) {
                atomicAdd(&red[r][hd0], vs0);
                atomicAdd(&red[r][4 + hd0], vd0);
                atomicAdd(&red[r][hd1], vs1);
                atomicAdd(&red[r][4 + hd1], vd1);
            }
        }
        __syncthreads();
        if (tid < 64) {
            int r = tid >> 2, hd = tid & 3;
            lsout[(r0 + r) * 4 + hd] = red[r][hd];
            ldout[(r0 + r) * 4 + hd] = red[r][4 + hd];
        }
    }
}

// ---------------- merged MLP head: gather+BN3+drop -> A1 -> LN+ReLU -> A2 -> LN+ReLU -> dot(A3)+tanh ----------------
__global__ void __launch_bounds__(64) k_head2(
    const float* __restrict__ X, const int* __restrict__ gidx,
    const float* __restrict__ A1, const float* __restrict__ ab1,
    const float* __restrict__ l1g, const float* __restrict__ l1b,
    const float* __restrict__ A2, const float* __restrict__ ab2,
    const float* __restrict__ l2g, const float* __restrict__ l2b,
    const float* __restrict__ A3v, const float* __restrict__ ab3v,
    const float* __restrict__ bnsum, const float* __restrict__ bng,
    const float* __restrict__ bnbe, unsigned key0, unsigned key1,
    float* __restrict__ logits) {
    __shared__ float sx[32 * 16];     // input k-major
    __shared__ float zs[16 * 132];    // A1 output rows (row-major, pad 132)
    __shared__ float z2[16 * 66];     // A2 output rows (row-major, pad 66)
    int r0 = blockIdx.x * 16;
    int tid = threadIdx.x;
    const float invN = 1.f / (float)NN;
    // stage 0: gather + BN3 + dropout2
    for (int i = tid; i < 16 * 32; i += 64) {
        int r = i & 15, k = i >> 4;
        int srow = gidx[r0 + r];
        float v = X[(size_t)srow * 32 + k];
        float mu = bnsum[k] * invN;
        float var = bnsum[32 + k] * invN - mu * mu;
        v = (v - mu) * rsqrtf(var + EPSV) * bng[k] + bnbe[k];
        unsigned bits = tf_xor(key0, key1, 0u, (unsigned)(srow * 32 + k));
        v = (bits & 0x80000000u) ? 0.f : 2.f * v;
        sx[k * 16 + r] = v;
    }
    __syncthreads();
    // stage 1: A1 (K=32 -> 128), 2 cols/thread
    {
        int j0 = tid, j1 = tid + 64;
        float acc0[16], acc1[16];
        float b0 = ab1[j0], b1 = ab1[j1];
#pragma unroll
        for (int r = 0; r < 16; r++) { acc0[r] = b0; acc1[r] = b1; }
#pragma unroll 4
        for (int k = 0; k < 32; k++) {
            float w0 = A1[(size_t)k * 128 + j0];
            float w1 = A1[(size_t)k * 128 + j1];
            const float4* xp = reinterpret_cast<const float4*>(sx + k * 16);
            float4 q0 = xp[0], q1 = xp[1], q2 = xp[2], q3 = xp[3];
            float xv[16] = {q0.x, q0.y, q0.z, q0.w, q1.x, q1.y, q1.z, q1.w,
                            q2.x, q2.y, q2.z, q2.w, q3.x, q3.y, q3.z, q3.w};
#pragma unroll
            for (int r = 0; r < 16; r++) {
                acc0[r] = fmaf(xv[r], w0, acc0[r]);
                acc1[r] = fmaf(xv[r], w1, acc1[r]);
            }
        }
#pragma unroll
        for (int r = 0; r < 16; r++) {
            zs[r * 132 + j0] = acc0[r];
            zs[r * 132 + j1] = acc1[r];
        }
    }
    __syncthreads();
    // stage 2: LN + ReLU per row (128 wide)
    {
        int w = tid >> 5, lane = tid & 31;
        for (int row = w; row < 16; row += 2) {
            float v[4];
            float s = 0.f, q = 0.f;
#pragma unroll
            for (int i = 0; i < 4; i++) {
                v[i] = zs[row * 132 + lane + 32 * i];
                s += v[i]; q = fmaf(v[i], v[i], q);
            }
#pragma unroll
            for (int o = 16; o > 0; o >>= 1) {
                s += __shfl_xor_sync(0xffffffffu, s, o);
                q += __shfl_xor_sync(0xffffffffu, q, o);
            }
            float mu = s / 128.f;
            float var = q / 128.f - mu * mu;
            float rs = rsqrtf(var + EPSV);
#pragma unroll
            for (int i = 0; i < 4; i++) {
                int c = lane + 32 * i;
                float y = (v[i] - mu) * rs * l1g[c] + l1b[c];
                zs[row * 132 + c] = fmaxf(y, 0.f);
            }
        }
    }
    __syncthreads();
    // stage 3: A2 (128 -> 64), 1 col/thread; float4 broadcast reads of zs
    {
        float acc[16];
        float b = ab2[tid];
#pragma unroll
        for (int r = 0; r < 16; r++) acc[r] = b;
        for (int q = 0; q < 32; q++) {
            float w0 = A2[(size_t)(4 * q + 0) * 64 + tid];
            float w1 = A2[(size_t)(4 * q + 1) * 64 + tid];
            float w2 = A2[(size_t)(4 * q + 2) * 64 + tid];
            float w3 = A2[(size_t)(4 * q + 3) * 64 + tid];
#pragma unroll
            for (int r = 0; r < 16; r++) {
                float4 zv = *reinterpret_cast<const float4*>(zs + r * 132 + 4 * q);
                acc[r] = fmaf(zv.x, w0, fmaf(zv.y, w1, fmaf(zv.z, w2, fmaf(zv.w, w3, acc[r]))));
            }
        }
#pragma unroll
        for (int r = 0; r < 16; r++) z2[r * 66 + tid] = acc[r];
    }
    __syncthreads();
    // stage 4: LN + ReLU + dot(A3) + tanh (warp 0)
    if (tid < 32) {
        int lane = tid;
        float a30 = A3v[lane], a31 = A3v[lane + 32];
        float bb = ab3v[0];
        for (int row = 0; row < 16; row++) {
            float v0 = z2[row * 66 + lane];
            float v1 = z2[row * 66 + lane + 32];
            float s = v0 + v1;
            float q = fmaf(v0, v0, v1 * v1);
#pragma unroll
            for (int o = 16; o > 0; o >>= 1) {
                s += __shfl_xor_sync(0xffffffffu, s, o);
                q += __shfl_xor_sync(0xffffffffu, q, o);
            }
            float mu = s / 64.f;
            float var = q / 64.f - mu * mu;
            float rs = rsqrtf(var + EPSV);
            float y0 = fmaxf((v0 - mu) * rs * l2g[lane] + l2b[lane], 0.f);
            float y1 = fmaxf((v1 - mu) * rs * l2g[lane + 32] + l2b[lane + 32], 0.f);
            float t = fmaf(y0, a30, y1 * a31);
#pragma unroll
            for (int o = 16; o > 0; o >>= 1) t += __shfl_xor_sync(0xffffffffu, t, o);
            if (lane == 0) logits[r0 + row] = tanhf(t + bb);
        }
    }
}

// ---------------- fused GAT softmax + aggregate: one node per block ----------------
template <int C>
__global__ void __launch_bounds__(2 * C) k_gat(
    const __half* __restrict__ h, const float* __restrict__ ls,
    const float* __restrict__ ldv, const int* __restrict__ off,
    const int* __restrict__ srcs, const float* __restrict__ bias,
    float* __restrict__ out) {
    constexpr int CHUNK = 64;
    __shared__ float s_alpha[CHUNK * 4];
    __shared__ int s_srcs[CHUNK];
    __shared__ float s_out[4 * C];
    int n = blockIdx.x;
    int t = threadIdx.x;
    int lane = t & 31;
    int start = off[n], end = off[n + 1];
    float m0 = -FLT_MAX, m1 = -FLT_MAX, m2 = -FLT_MAX, m3 = -FLT_MAX;
    float rd0 = 0.f, rd1 = 0.f, rd2 = 0.f, rd3 = 0.f;
    float ldx = 0.f, ldy = 0.f, ldz = 0.f, ldw = 0.f;
    if (t < 32) {
        float4 ldq = *reinterpret_cast<const float4*>(ldv + n * 4);
        ldx = ldq.x; ldy = ldq.y; ldz = ldq.z; ldw = ldq.w;
        for (int e = start + lane; e < end; e += 32) {
            int s = srcs[e];
            float4 lv = *reinterpret_cast<const float4*>(ls + s * 4);
            m0 = fmaxf(m0, lrelu02(lv.x + ldx));
            m1 = fmaxf(m1, lrelu02(lv.y + ldy));
            m2 = fmaxf(m2, lrelu02(lv.z + ldz));
            m3 = fmaxf(m3, lrelu02(lv.w + ldw));
        }
#pragma unroll
        for (int o = 16; o > 0; o >>= 1) {
            m0 = fmaxf(m0, __shfl_xor_sync(0xffffffffu, m0, o));
            m1 = fmaxf(m1, __shfl_xor_sync(0xffffffffu, m1, o));
            m2 = fmaxf(m2, __shfl_xor_sync(0xffffffffu, m2, o));
            m3 = fmaxf(m3, __shfl_xor_sync(0xffffffffu, m3, o));
        }
        float d0 = 0.f, d1 = 0.f, d2 = 0.f, d3 = 0.f;
        for (int e = start + lane; e < end; e += 32) {
            int s = srcs[e];
            float4 lv = *reinterpret_cast<const float4*>(ls + s * 4);
            d0 += expf(lrelu02(lv.x + ldx) - m0);
            d1 += expf(lrelu02(lv.y + ldy) - m1);
            d2 += expf(lrelu02(lv.z + ldz) - m2);
            d3 += expf(lrelu02(lv.w + ldw) - m3);
        }
#pragma unroll
        for (int o = 16; o > 0; o >>= 1) {
            d0 += __shfl_xor_sync(0xffffffffu, d0, o);
            d1 += __shfl_xor_sync(0xffffffffu, d1, o);
            d2 += __shfl_xor_sync(0xffffffffu, d2, o);
            d3 += __shfl_xor_sync(0xffffffffu, d3, o);
        }
        rd0 = 0.25f / d0; rd1 = 0.25f / d1; rd2 = 0.25f / d2; rd3 = 0.25f / d3;
    }
    int head = t / (C / 2);
    int pair = t % (C / 2);
    float accx = 0.f, accy = 0.f;
    for (int cs = start; cs < end; cs += CHUNK) {
        int ce = min(cs + CHUNK, end);
        if (t < 32) {
            for (int e = cs + lane; e < ce; e += 32) {
                int s = srcs[e];
                float4 lv = *reinterpret_cast<const float4*>(ls + s * 4);
                int i = e - cs;
                s_srcs[i] = s;
                s_alpha[i * 4 + 0] = expf(lrelu02(lv.x + ldx) - m0) * rd0;
                s_alpha[i * 4 + 1] = expf(lrelu02(lv.y + ldy) - m1) * rd1;
                s_alpha[i * 4 + 2] = expf(lrelu02(lv.z + ldz) - m2) * rd2;
                s_alpha[i * 4 + 3] = expf(lrelu02(lv.w + ldw) - m3) * rd3;
            }
        }
        __syncthreads();
        int cnt = ce - cs;
        int i = 0;
        for (; i + 2 <= cnt; i += 2) {
            int s0 = s_srcs[i], s1 = s_srcs[i + 1];
            float a0 = s_alpha[i * 4 + head];
            float a1 = s_alpha[(i + 1) * 4 + head];
            __half2 v0 = *reinterpret_cast<const __half2*>(h + ((size_t)s0 * 4 + head) * C + 2 * pair);
            __half2 v1 = *reinterpret_cast<const __half2*>(h + ((size_t)s1 * 4 + head) * C + 2 * pair);
            float2 f0 = __half22float2(v0), f1 = __half22float2(v1);
            accx = fmaf(f0.x, a0, fmaf(f1.x, a1, accx));
            accy = fmaf(f0.y, a0, fmaf(f1.y, a1, accy));
        }
        if (i < cnt) {
            int s0 = s_srcs[i];
            float a0 = s_alpha[i * 4 + head];
            float2 f0 = __half22float2(
                *reinterpret_cast<const __half2*>(h + ((size_t)s0 * 4 + head) * C + 2 * pair));
            accx = fmaf(f0.x, a0, accx);
            accy = fmaf(f0.y, a0, accy);
        }
        __syncthreads();
    }
    s_out[head * C + 2 * pair] = accx;
    s_out[head * C + 2 * pair + 1] = accy;
    __syncthreads();
    if (t < C) {
        float v = (s_out[t] + s_out[C + t]) + (s_out[2 * C + t] + s_out[3 * C + t]) + bias[t];
        out[(size_t)n * C + t] = v;
    }
}

// ---------------- BN stats ----------------
__global__ void k_bn_stats(const float* __restrict__ x, int N, int C, float* __restrict__ sums) {
    int t = threadIdx.x;
    int r0 = blockIdx.x * 256;
    int r1 = min(r0 + 256, N);
    float s = 0.f, q = 0.f;
    for (int r = r0; r < r1; r++) {
        float v = x[(size_t)r * C + t];
        s += v; q = fmaf(v, v, q);
    }
    atomicAdd(&sums[t], s);
    atomicAdd(&sums[C + t], q);
}

// ---------------- softmax ----------------
__global__ void k_smax_part(const float* __restrict__ lg, int n, float* __restrict__ part) {
    __shared__ float sm[256], ss[256];
    float m = -FLT_MAX, s = 0.f;
    for (int i = blockIdx.x * 256 + threadIdx.x; i < n; i += 128 * 256) {
        float v = lg[i];
        float nm = fmaxf(m, v);
        s = s * expf(m - nm) + expf(v - nm);
        m = nm;
    }
    sm[threadIdx.x] = m; ss[threadIdx.x] = s;
    __syncthreads();
    for (int o = 128; o > 0; o >>= 1) {
        if (threadIdx.x < o) {
            float m2 = sm[threadIdx.x + o], s2 = ss[threadIdx.x + o];
            float nm = fmaxf(sm[threadIdx.x], m2);
            ss[threadIdx.x] = ss[threadIdx.x] * expf(sm[threadIdx.x] - nm) + s2 * expf(m2 - nm);
            sm[threadIdx.x] = nm;
        }
        __syncthreads();
    }
    if (threadIdx.x == 0) { part[blockIdx.x] = sm[0]; part[128 + blockIdx.x] = ss[0]; }
}
__global__ void k_smax_fin(const float* __restrict__ lg, int n,
                           const float* __restrict__ part, float* __restrict__ out) {
    __shared__ float sm[128], ss[128];
    __shared__ float fM, fS;
    int t = threadIdx.x;
    if (t < 128) { sm[t] = part[t]; ss[t] = part[128 + t]; }
    __syncthreads();
    for (int o = 64; o > 0; o >>= 1) {
        if (t < o) {
            float m2 = sm[t + o], s2 = ss[t + o];
            float nm = fmaxf(sm[t], m2);
            ss[t] = ss[t] * expf(sm[t] - nm) + s2 * expf(m2 - nm);
            sm[t] = nm;
        }
        __syncthreads();
    }
    if (t == 0) { fM = sm[0]; fS = ss[0]; }
    __syncthreads();
    float M = fM, S = fS;
    for (int i = t; i < n; i += 1024) {
        float l = lg[i];
        out[i] = l;
        out[n + i] = expf(l - M) / S;
    }
}

// ---------------- launch ----------------
extern "C" void kernel_launch(void* const* d_in, const int* in_sizes, int n_in,
                              void* d_out, int out_size) {
    const float* x   = (const float*)d_in[0];
    const int* ei    = (const int*)d_in[1];
    int E = in_sizes[1] / 2;
    const int* esrc = ei;
    const int* edst = ei + E;
    const float* W1  = (const float*)d_in[2];
    const float* as1 = (const float*)d_in[3];
    const float* ad1 = (const float*)d_in[4];
    const float* b1  = (const float*)d_in[5];
    const float* g1  = (const float*)d_in[6];
    const float* be1 = (const float*)d_in[7];
    const float* W2  = (const float*)d_in[8];
    const float* as2 = (const float*)d_in[9];
    const float* ad2 = (const float*)d_in[10];
    const float* b2  = (const float*)d_in[11];
    const float* g2  = (const float*)d_in[12];
    const float* be2 = (const float*)d_in[13];
    const float* W3  = (const float*)d_in[14];
    const float* as3 = (const float*)d_in[15];
    const float* ad3 = (const float*)d_in[16];
    const float* b3  = (const float*)d_in[17];
    const float* g3  = (const float*)d_in[18];
    const float* be3 = (const float*)d_in[19];
    const float* A1  = (const float*)d_in[20];
    const float* ab1 = (const float*)d_in[21];
    const float* l1g = (const float*)d_in[22];
    const float* l1b = (const float*)d_in[23];
    const float* A2  = (const float*)d_in[24];
    const float* ab2 = (const float*)d_in[25];
    const float* l2g = (const float*)d_in[26];
    const float* l2b = (const float*)d_in[27];
    const float* A3  = (const float*)d_in[28];
    const float* ab3 = (const float*)d_in[29];

    __half* h;
    float *io0, *io1, *ls, *ld, *logits, *bn, *part;
    int *deg, *off, *cur, *srcs, *bsum;
    cudaGetSymbolAddress((void**)&h, g_h);
    cudaGetSymbolAddress((void**)&io0, g_io0);
    cudaGetSymbolAddress((void**)&io1, g_io1);
    cudaGetSymbolAddress((void**)&ls, g_ls);
    cudaGetSymbolAddress((void**)&ld, g_ld);
    cudaGetSymbolAddress((void**)&logits, g_logits);
    cudaGetSymbolAddress((void**)&bn, g_bn);
    cudaGetSymbolAddress((void**)&part, g_part);
    cudaGetSymbolAddress((void**)&deg, g_deg);
    cudaGetSymbolAddress((void**)&off, g_off);
    cudaGetSymbolAddress((void**)&cur, g_cur);
    cudaGetSymbolAddress((void**)&srcs, g_srcs);
    cudaGetSymbolAddress((void**)&bsum, g_bsum);

    unsigned dk[3][2];
    for (unsigned i = 0; i < 3; i++) tf_host(0u, 42u, 0u, i, &dk[i][0], &dk[i][1]);

    const int nb = (NN + 255) / 256;  // 196
    const int NG = NN / 16;           // 3125

    // ---- layer-1 coef + global init (deg=1, bn=0) ----
    k_coef1<<<nb, 256>>>(x, W1, as1, ad1, ls, ld, NN, deg, bn);

    // ---- CSR build ----
    k_count<<<(E + 255) / 256, 256>>>(edst, E, deg);
    k_scan1<<<nb, 256>>>(deg, off, bsum, NN);
    k_scan2<<<1, 256>>>(bsum, nb, off + NN);
    k_scan3<0><<<nb, 256>>>(off, bsum, cur, NN);
    k_scatter<<<(E + NN + 255) / 256, 256>>>(esrc, edst, E, NN, cur, srcs);

    // ---- layer 1: aggregate-then-project ----
    k_gat1agg<<<(NN + 7) / 8, 256>>>(x, ls, ld, off, srcs, io1);
    k_out1<<<NG, 128>>>(io1, W1, b1, io0, bn);

    // ---- layer 2: BN1+ELU+drop0 fused; 128 -> 4x64 + coef ----
    k_gemm<128, 256, 128, 1, 1, 1><<<NG, 128, 16 * 128 * 4>>>(
        io0, 128, 0, nullptr, W2, nullptr, nullptr, h,
        bn, g1, be1, dk[0][0], dk[0][1], as2, ad2, ls, ld);
    k_gat<64><<<NN, 128>>>(h, ls, ld, off, srcs, b2, io1);
    k_bn_stats<<<nb, 64>>>(io1, NN, 64, bn + 256);

    // ---- layer 3: BN2+ELU+drop1 fused; 64 -> 4x32 + coef ----
    k_gemm<64, 128, 64, 1, 1, 1><<<NG, 64, 16 * 64 * 4>>>(
        io1, 64, 0, nullptr, W3, nullptr, nullptr, h,
        bn + 256, g2, be2, dk[1][0], dk[1][1], as3, ad3, ls, ld);
    k_gat<32><<<NN, 64>>>(h, ls, ld, off, srcs, b3, io0);
    k_bn_stats<<<nb, 32>>>(io0, NN, 32, bn + 384);

    // ---- selection ----
    k_scan1_cond<<<nb, 256>>>(x, off, bsum, NN);
    k_scan2<<<1, 256>>>(bsum, nb, nullptr);
    k_scan3<1><<<nb, 256>>>(off, bsum, cur, NN);
    k_idx_scatter<<<nb, 256>>>(x, off, cur, NN);

    // ---- merged MLP head ----
    k_head2<<<NG, 64>>>(io0, cur, A1, ab1, l1g, l1b, A2, ab2, l2g, l2b, A3, ab3,
                        bn + 384, g3, be3, dk[2][0], dk[2][1], logits);

    // ---- softmax ----
    k_smax_part<<<128, 256>>>(logits, NN, part);
    k_smax_fin<<<1, 1024>>>(logits, NN, part, (float*)d_out);
}

// round 14
// speedup vs baseline: 1.1329x; 1.0428x over previous
#include <cuda_runtime.h>
#include <cuda_fp16.h>
#include <math.h>
#include <float.h>
#include <stdint.h>

#define NN 50000
#define EE 400000
#define EPSV 1e-5f

// ---------------- scratch ----------------
__device__ __half g_h[(size_t)NN * 512];
__device__ float g_io0[(size_t)NN * 128];
__device__ float g_io1[(size_t)NN * 128];   // also reused as agg[NN][16]
__device__ float g_ls[NN * 4];
__device__ float g_ld[NN * 4];
__device__ float g_logits[NN];
__device__ float g_bn[448];
__device__ float g_part[4];     // [0] = sum exp(l-1)
__device__ int   g_deg[NN];     // CSR degree, then reused as selection idx buffer
__device__ int   g_off[NN + 1];
__device__ int   g_cur[NN];
__device__ int   g_pos[NN];     // selection block-local prefix
__device__ int   g_srcs[EE + NN];
__device__ int   g_bsum[256];
__device__ int   g_bsum2[256];

// ---------------- threefry2x32 (partitionable xor bits) ----------------
__device__ __forceinline__ unsigned rotl32d(unsigned v, int r) {
    return __funnelshift_l(v, v, r);
}
__device__ __forceinline__ unsigned tf_xor(unsigned k0, unsigned k1, unsigned x0, unsigned x1) {
    unsigned k2 = k0 ^ k1 ^ 0x1BD11BDAu;
    x0 += k0; x1 += k1;
#define TF_R(r) { x0 += x1; x1 = rotl32d(x1, r); x1 ^= x0; }
    TF_R(13) TF_R(15) TF_R(26) TF_R(6)   x0 += k1; x1 += k2 + 1u;
    TF_R(17) TF_R(29) TF_R(16) TF_R(24)  x0 += k2; x1 += k0 + 2u;
    TF_R(13) TF_R(15) TF_R(26) TF_R(6)   x0 += k0; x1 += k1 + 3u;
    TF_R(17) TF_R(29) TF_R(16) TF_R(24)  x0 += k1; x1 += k2 + 4u;
    TF_R(13) TF_R(15) TF_R(26) TF_R(6)   x0 += k2; x1 += k0 + 5u;
#undef TF_R
    return x0 ^ x1;
}
static inline unsigned rotl32h(unsigned v, int r) { return (v << r) | (v >> (32 - r)); }
static void tf_host(unsigned k0, unsigned k1, unsigned x0, unsigned x1,
                    unsigned* o0, unsigned* o1) {
    unsigned k2 = k0 ^ k1 ^ 0x1BD11BDAu;
    x0 += k0; x1 += k1;
#define TF_RH(r) { x0 += x1; x1 = rotl32h(x1, r); x1 ^= x0; }
    TF_RH(13) TF_RH(15) TF_RH(26) TF_RH(6)   x0 += k1; x1 += k2 + 1u;
    TF_RH(17) TF_RH(29) TF_RH(16) TF_RH(24)  x0 += k2; x1 += k0 + 2u;
    TF_RH(13) TF_RH(15) TF_RH(26) TF_RH(6)   x0 += k0; x1 += k1 + 3u;
    TF_RH(17) TF_RH(29) TF_RH(16) TF_RH(24)  x0 += k1; x1 += k2 + 4u;
    TF_RH(13) TF_RH(15) TF_RH(26) TF_RH(6)   x0 += k2; x1 += k0 + 5u;
#undef TF_RH
    *o0 = x0; *o1 = x1;
}

__global__ void k_count(const int* __restrict__ dst, int e, int* deg) {
    int i = blockIdx.x * blockDim.x + threadIdx.x;
    if (i < e) atomicAdd(&deg[dst[i]], 1);
}

// ---------------- scans ----------------
__global__ void k_scan1(const int* __restrict__ in, int* __restrict__ out,
                        int* __restrict__ bsum, int n) {
    __shared__ int sh[256];
    int i = blockIdx.x * 256 + threadIdx.x;
    int t = threadIdx.x;
    int v = (i < n) ? in[i] : 0;
    sh[t] = v;
    __syncthreads();
#pragma unroll
    for (int o = 1; o < 256; o <<= 1) {
        int add = (t >= o) ? sh[t - o] : 0;
        __syncthreads();
        sh[t] += add;
        __syncthreads();
    }
    if (i < n) out[i] = sh[t] - v;
    if (t == 255) bsum[blockIdx.x] = sh[255];
}
// dual exclusive scan of two block-sum arrays (nb <= 256)
__global__ void k_scan2_dual(int* __restrict__ bsum, int nb, int* __restrict__ total,
                             int* __restrict__ bsum2) {
    __shared__ int sh[256];
    int t = threadIdx.x;
    int v = (t < nb) ? bsum[t] : 0;
    sh[t] = v;
    __syncthreads();
#pragma unroll
    for (int o = 1; o < 256; o <<= 1) {
        int add = (t >= o) ? sh[t - o] : 0;
        __syncthreads();
        sh[t] += add;
        __syncthreads();
    }
    if (t < nb) bsum[t] = sh[t] - v;
    if (t == 0 && total) *total = sh[255];
    __syncthreads();
    int v2 = (t < nb) ? bsum2[t] : 0;
    sh[t] = v2;
    __syncthreads();
#pragma unroll
    for (int o = 1; o < 256; o <<= 1) {
        int add = (t >= o) ? sh[t - o] : 0;
        __syncthreads();
        sh[t] += add;
        __syncthreads();
    }
    if (t < nb) bsum2[t] = sh[t] - v2;
}
// CSR scan finalize + cursor init + zero deg (deg becomes selection idx buffer)
__global__ void k_scan3(int* __restrict__ out, const int* __restrict__ bsum,
                        int* __restrict__ cur, int* __restrict__ deg, int n) {
    int i = blockIdx.x * 256 + threadIdx.x;
    if (i < n) {
        int v = out[i] + bsum[blockIdx.x];
        out[i] = v;
        cur[i] = v;
        deg[i] = 0;
    }
}
__global__ void k_scatter(const int* __restrict__ src, const int* __restrict__ dst,
                          int e, int n, int* cur, int* __restrict__ outsrc) {
    int i = blockIdx.x * blockDim.x + threadIdx.x;
    if (i < e) {
        int p = atomicAdd(&cur[dst[i]], 1);
        outsrc[p] = src[i];
    } else if (i < e + n) {
        int nd = i - e;
        int p = atomicAdd(&cur[nd], 1);
        outsrc[p] = nd;
    }
}
// selection scatter: idx (=deg buffer) [posglobal] = i for cond rows
__global__ void k_selfin(const float* __restrict__ x, const int* __restrict__ pos,
                         const int* __restrict__ bsum2, int* __restrict__ idx, int n) {
    int i = blockIdx.x * 256 + threadIdx.x;
    if (i < n && x[i * 6 + 2] == 1.0f && x[i * 6 + 5] == 0.0f)
        idx[pos[i] + bsum2[blockIdx.x]] = i;
}

__device__ __forceinline__ float lrelu02(float v) { return v > 0.f ? v : 0.2f * v; }

// ---------------- layer-1 coef + init + selection scan stage1 ----------------
__global__ void k_coef1(const float* __restrict__ x, const float* __restrict__ W1,
                        const float* __restrict__ as1, const float* __restrict__ ad1,
                        float* __restrict__ ls, float* __restrict__ ld, int n,
                        int* __restrict__ deg, float* __restrict__ bnz,
                        int* __restrict__ pos, int* __restrict__ bsum2,
                        float* __restrict__ part) {
    __shared__ float fold[32];
    __shared__ int sh[256];
    int t = threadIdx.x;
    int i = blockIdx.x * 256 + t;
    if (i < n) deg[i] = 1;
    if (i < 448) bnz[i] = 0.f;
    if (i == 0) part[0] = 0.f;
    int c = 0;
    float x0 = 0.f, x1 = 0.f, x2 = 0.f, x3 = 0.f;
    if (i < n) {
        x0 = x[i * 6 + 1]; x1 = x[i * 6 + 2]; x2 = x[i * 6 + 3]; x3 = x[i * 6 + 4];
        c = (x1 == 1.0f && x[i * 6 + 5] == 0.0f) ? 1 : 0;
    }
    sh[t] = c;
    if (t < 32) {
        int h = (t & 15) >> 2, k = t & 3;
        const float* a = (t < 16) ? as1 : ad1;
        float s = 0.f;
        for (int cc = 0; cc < 128; cc++)
            s = fmaf(W1[k * 512 + h * 128 + cc], a[h * 128 + cc], s);
        fold[t] = s;
    }
    __syncthreads();
#pragma unroll
    for (int o = 1; o < 256; o <<= 1) {
        int add = (t >= o) ? sh[t - o] : 0;
        __syncthreads();
        sh[t] += add;
        __syncthreads();
    }
    if (i < n) pos[i] = sh[t] - c;
    if (t == 255) bsum2[blockIdx.x] = sh[255];
    if (i >= n) return;
#pragma unroll
    for (int h = 0; h < 4; h++) {
        float s = fmaf(x0, fold[h * 4 + 0], fmaf(x1, fold[h * 4 + 1],
                  fmaf(x2, fold[h * 4 + 2], x3 * fold[h * 4 + 3])));
        float d = fmaf(x0, fold[16 + h * 4 + 0], fmaf(x1, fold[16 + h * 4 + 1],
                  fmaf(x2, fold[16 + h * 4 + 2], x3 * fold[16 + h * 4 + 3])));
        ls[i * 4 + h] = s;
        ld[i * 4 + h] = d;
    }
}

// ---------------- layer-1 aggregate in input space: warp per dst node ----------------
__global__ void __launch_bounds__(256) k_gat1agg(
    const float* __restrict__ x, const float* __restrict__ ls,
    const float* __restrict__ ldv, const int* __restrict__ off,
    const int* __restrict__ srcs, float* __restrict__ agg) {
    int n = blockIdx.x * 8 + (threadIdx.x >> 5);
    int lane = threadIdx.x & 31;
    if (n >= NN) return;
    int start = off[n], end = off[n + 1];
    float4 ldq = *reinterpret_cast<const float4*>(ldv + n * 4);
    float m0 = -FLT_MAX, m1 = -FLT_MAX, m2 = -FLT_MAX, m3 = -FLT_MAX;
    for (int e = start + lane; e < end; e += 32) {
        int s = srcs[e];
        float4 lv = *reinterpret_cast<const float4*>(ls + s * 4);
        m0 = fmaxf(m0, lrelu02(lv.x + ldq.x));
        m1 = fmaxf(m1, lrelu02(lv.y + ldq.y));
        m2 = fmaxf(m2, lrelu02(lv.z + ldq.z));
        m3 = fmaxf(m3, lrelu02(lv.w + ldq.w));
    }
#pragma unroll
    for (int o = 16; o > 0; o >>= 1) {
        m0 = fmaxf(m0, __shfl_xor_sync(0xffffffffu, m0, o));
        m1 = fmaxf(m1, __shfl_xor_sync(0xffffffffu, m1, o));
        m2 = fmaxf(m2, __shfl_xor_sync(0xffffffffu, m2, o));
        m3 = fmaxf(m3, __shfl_xor_sync(0xffffffffu, m3, o));
    }
    float d0 = 0.f, d1 = 0.f, d2 = 0.f, d3 = 0.f;
    for (int e = start + lane; e < end; e += 32) {
        int s = srcs[e];
        float4 lv = *reinterpret_cast<const float4*>(ls + s * 4);
        d0 += expf(lrelu02(lv.x + ldq.x) - m0);
        d1 += expf(lrelu02(lv.y + ldq.y) - m1);
        d2 += expf(lrelu02(lv.z + ldq.z) - m2);
        d3 += expf(lrelu02(lv.w + ldq.w) - m3);
    }
#pragma unroll
    for (int o = 16; o > 0; o >>= 1) {
        d0 += __shfl_xor_sync(0xffffffffu, d0, o);
        d1 += __shfl_xor_sync(0xffffffffu, d1, o);
        d2 += __shfl_xor_sync(0xffffffffu, d2, o);
        d3 += __shfl_xor_sync(0xffffffffu, d3, o);
    }
    float rd0 = 0.25f / d0, rd1 = 0.25f / d1, rd2 = 0.25f / d2, rd3 = 0.25f / d3;
    float acc[16];
#pragma unroll
    for (int i = 0; i < 16; i++) acc[i] = 0.f;
    for (int e = start + lane; e < end; e += 32) {
        int s = srcs[e];
        float4 lv = *reinterpret_cast<const float4*>(ls + s * 4);
        float a0 = expf(lrelu02(lv.x + ldq.x) - m0) * rd0;
        float a1 = expf(lrelu02(lv.y + ldq.y) - m1) * rd1;
        float a2 = expf(lrelu02(lv.z + ldq.z) - m2) * rd2;
        float a3 = expf(lrelu02(lv.w + ldq.w) - m3) * rd3;
        const float* xr = x + (size_t)s * 6 + 1;
        float xv0 = xr[0], xv1 = xr[1], xv2 = xr[2], xv3 = xr[3];
        acc[0]  = fmaf(a0, xv0, acc[0]);  acc[1]  = fmaf(a0, xv1, acc[1]);
        acc[2]  = fmaf(a0, xv2, acc[2]);  acc[3]  = fmaf(a0, xv3, acc[3]);
        acc[4]  = fmaf(a1, xv0, acc[4]);  acc[5]  = fmaf(a1, xv1, acc[5]);
        acc[6]  = fmaf(a1, xv2, acc[6]);  acc[7]  = fmaf(a1, xv3, acc[7]);
        acc[8]  = fmaf(a2, xv0, acc[8]);  acc[9]  = fmaf(a2, xv1, acc[9]);
        acc[10] = fmaf(a2, xv2, acc[10]); acc[11] = fmaf(a2, xv3, acc[11]);
        acc[12] = fmaf(a3, xv0, acc[12]); acc[13] = fmaf(a3, xv1, acc[13]);
        acc[14] = fmaf(a3, xv2, acc[14]); acc[15] = fmaf(a3, xv3, acc[15]);
    }
#pragma unroll
    for (int i = 0; i < 16; i++) {
#pragma unroll
        for (int o = 16; o > 0; o >>= 1)
            acc[i] += __shfl_xor_sync(0xffffffffu, acc[i], o);
    }
    if (lane == 0) {
#pragma unroll
        for (int i = 0; i < 16; i++) agg[(size_t)n * 16 + i] = acc[i];
    }
}

// ---------------- layer-1 output projection + fused BN stats ----------------
__global__ void __launch_bounds__(128) k_out1(
    const float* __restrict__ agg, const float* __restrict__ W1,
    const float* __restrict__ b1, float* __restrict__ out, float* __restrict__ bnsum) {
    __shared__ float sA[256];
    int r0 = blockIdx.x * 16;
    int t = threadIdx.x;
    for (int i = t; i < 256; i += 128) sA[i] = agg[(size_t)r0 * 16 + i];
    __syncthreads();
    float w[16];
#pragma unroll
    for (int h = 0; h < 4; h++)
#pragma unroll
        for (int k = 0; k < 4; k++)
            w[h * 4 + k] = W1[k * 512 + h * 128 + t];
    float b = b1[t];
    float s = 0.f, q = 0.f;
#pragma unroll
    for (int r = 0; r < 16; r++) {
        float acc = b;
#pragma unroll
        for (int i = 0; i < 16; i++) acc = fmaf(sA[r * 16 + i], w[i], acc);
        out[(size_t)(r0 + r) * 128 + t] = acc;
        s += acc;
        q = fmaf(acc, acc, q);
    }
    atomicAdd(&bnsum[t], s);
    atomicAdd(&bnsum[128 + t], q);
}

// ---------------- fused GEMM (R10 config) ----------------
template <int KK, int MM, int BD, int PRE, int POST, int COEF>
__global__ void __launch_bounds__(BD) k_gemm(
    const float* __restrict__ X, int ldx, int xcol0, const int* __restrict__ gidx,
    const float* __restrict__ W, const float* __restrict__ bias,
    float* __restrict__ Yf, __half* __restrict__ Yh,
    const float* __restrict__ bnsum, const float* __restrict__ bng,
    const float* __restrict__ bnbe, unsigned key0, unsigned key1,
    const float* __restrict__ as_, const float* __restrict__ ad_,
    float* __restrict__ lsout, float* __restrict__ ldout) {
    static_assert(MM == 2 * BD, "MM must be 2*BD");
    extern __shared__ float xs[];
    __shared__ float red[16][8];
    int r0 = blockIdx.x * 16;
    int tid = threadIdx.x;
    const float invN = 1.f / (float)NN;
    if (COEF) {
        for (int i = tid; i < 128; i += BD) red[i >> 3][i & 7] = 0.f;
    }
    for (int i = tid; i < 16 * KK; i += BD) {
        int r = i & 15, k = i >> 4;
        int row = r0 + r;
        int srow = (gidx != nullptr) ? gidx[row] : row;
        float v = X[(size_t)srow * ldx + xcol0 + k];
        if (PRE > 0) {
            float mu = bnsum[k] * invN;
            float var = bnsum[KK + k] * invN - mu * mu;
            v = (v - mu) * rsqrtf(var + EPSV) * bng[k] + bnbe[k];
            if (PRE == 1) v = v > 0.f ? v : expm1f(v);
            unsigned bits = tf_xor(key0, key1, 0u, (unsigned)(srow * KK + k));
            v = (bits & 0x80000000u) ? 0.f : 2.f * v;
        }
        xs[k * 16 + r] = v;
    }
    __syncthreads();
    int j0 = tid, j1 = tid + BD;
    float acc0[16], acc1[16];
    float b0 = bias ? bias[j0] : 0.f;
    float b1 = bias ? bias[j1] : 0.f;
#pragma unroll
    for (int r = 0; r < 16; r++) { acc0[r] = b0; acc1[r] = b1; }
#pragma unroll 4
    for (int k = 0; k < KK; k++) {
        float w0 = W[(size_t)k * MM + j0];
        float w1 = W[(size_t)k * MM + j1];
        const float4* xp = reinterpret_cast<const float4*>(xs + k * 16);
        float4 q0 = xp[0], q1 = xp[1], q2 = xp[2], q3 = xp[3];
        float xv[16] = {q0.x, q0.y, q0.z, q0.w, q1.x, q1.y, q1.z, q1.w,
                        q2.x, q2.y, q2.z, q2.w, q3.x, q3.y, q3.z, q3.w};
#pragma unroll
        for (int r = 0; r < 16; r++) {
            acc0[r] = fmaf(xv[r], w0, acc0[r]);
            acc1[r] = fmaf(xv[r], w1, acc1[r]);
        }
    }
    if (POST == 1) {
#pragma unroll
        for (int r = 0; r < 16; r++) {
            Yh[(size_t)(r0 + r) * MM + j0] = __float2half_rn(acc0[r]);
            Yh[(size_t)(r0 + r) * MM + j1] = __float2half_rn(acc1[r]);
        }
    }
    if (COEF) {
        constexpr int C = MM / 4;
        int hd0 = j0 / C, hd1 = j1 / C;
        float as0 = as_[hd0 * C + (j0 % C)], ad0 = ad_[hd0 * C + (j0 % C)];
        float as1v = as_[hd1 * C + (j1 % C)], ad1v = ad_[hd1 * C + (j1 % C)];
        int lane = tid & 31;
#pragma unroll
        for (int r = 0; r < 16; r++) {
            float vs0 = acc0[r] * as0;
            float vd0 = acc0[r] * ad0;
            float vs1 = acc1[r] * as1v;
            float vd1 = acc1[r] * ad1v;
#pragma unroll
            for (int o = 16; o > 0; o >>= 1) {
                vs0 += __shfl_xor_sync(0xffffffffu, vs0, o);
                vd0 += __shfl_xor_sync(0xffffffffu, vd0, o);
                vs1 += __shfl_xor_sync(0xffffffffu, vs1, o);
                vd1 += __shfl_xor_sync(0xffffffffu, vd1, o);
            }
            if (lane == 0) {
                atomicAdd(&red[r][hd0], vs0);
                atomicAdd(&red[r][4 + hd0], vd0);
                atomicAdd(&red[r][hd1], vs1);
                atomicAdd(&red[r][4 + hd1], vd1);
            }
        }
        __syncthreads();
        if (tid < 64) {
            int r = tid >> 2, hd = tid & 3;
            lsout[(r0 + r) * 4 + hd] = red[r][hd];
            ldout[(r0 + r) * 4 + hd] = red[r][4 + hd];
        }
    }
}

// ---------------- merged MLP head + exp-sum accumulation ----------------
__global__ void __launch_bounds__(64) k_head2(
    const float* __restrict__ X, const int* __restrict__ gidx,
    const float* __restrict__ A1, const float* __restrict__ ab1,
    const float* __restrict__ l1g, const float* __restrict__ l1b,
    const float* __restrict__ A2, const float* __restrict__ ab2,
    const float* __restrict__ l2g, const float* __restrict__ l2b,
    const float* __restrict__ A3v, const float* __restrict__ ab3v,
    const float* __restrict__ bnsum, const float* __restrict__ bng,
    const float* __restrict__ bnbe, unsigned key0, unsigned key1,
    float* __restrict__ logits, float* __restrict__ part) {
    __shared__ float sx[32 * 16];
    __shared__ float zs[16 * 132];
    __shared__ float z2[16 * 66];
    int r0 = blockIdx.x * 16;
    int tid = threadIdx.x;
    const float invN = 1.f / (float)NN;
    for (int i = tid; i < 16 * 32; i += 64) {
        int r = i & 15, k = i >> 4;
        int srow = gidx[r0 + r];
        float v = X[(size_t)srow * 32 + k];
        float mu = bnsum[k] * invN;
        float var = bnsum[32 + k] * invN - mu * mu;
        v = (v - mu) * rsqrtf(var + EPSV) * bng[k] + bnbe[k];
        unsigned bits = tf_xor(key0, key1, 0u, (unsigned)(srow * 32 + k));
        v = (bits & 0x80000000u) ? 0.f : 2.f * v;
        sx[k * 16 + r] = v;
    }
    __syncthreads();
    {
        int j0 = tid, j1 = tid + 64;
        float acc0[16], acc1[16];
        float b0 = ab1[j0], b1 = ab1[j1];
#pragma unroll
        for (int r = 0; r < 16; r++) { acc0[r] = b0; acc1[r] = b1; }
#pragma unroll 4
        for (int k = 0; k < 32; k++) {
            float w0 = A1[(size_t)k * 128 + j0];
            float w1 = A1[(size_t)k * 128 + j1];
            const float4* xp = reinterpret_cast<const float4*>(sx + k * 16);
            float4 q0 = xp[0], q1 = xp[1], q2 = xp[2], q3 = xp[3];
            float xv[16] = {q0.x, q0.y, q0.z, q0.w, q1.x, q1.y, q1.z, q1.w,
                            q2.x, q2.y, q2.z, q2.w, q3.x, q3.y, q3.z, q3.w};
#pragma unroll
            for (int r = 0; r < 16; r++) {
                acc0[r] = fmaf(xv[r], w0, acc0[r]);
                acc1[r] = fmaf(xv[r], w1, acc1[r]);
            }
        }
#pragma unroll
        for (int r = 0; r < 16; r++) {
            zs[r * 132 + j0] = acc0[r];
            zs[r * 132 + j1] = acc1[r];
        }
    }
    __syncthreads();
    {
        int w = tid >> 5, lane = tid & 31;
        for (int row = w; row < 16; row += 2) {
            float v[4];
            float s = 0.f, q = 0.f;
#pragma unroll
            for (int i = 0; i < 4; i++) {
                v[i] = zs[row * 132 + lane + 32 * i];
                s += v[i]; q = fmaf(v[i], v[i], q);
            }
#pragma unroll
            for (int o = 16; o > 0; o >>= 1) {
                s += __shfl_xor_sync(0xffffffffu, s, o);
                q += __shfl_xor_sync(0xffffffffu, q, o);
            }
            float mu = s / 128.f;
            float var = q / 128.f - mu * mu;
            float rs = rsqrtf(var + EPSV);
#pragma unroll
            for (int i = 0; i < 4; i++) {
                int c = lane + 32 * i;
                float y = (v[i] - mu) * rs * l1g[c] + l1b[c];
                zs[row * 132 + c] = fmaxf(y, 0.f);
            }
        }
    }
    __syncthreads();
    {
        float acc[16];
        float b = ab2[tid];
#pragma unroll
        for (int r = 0; r < 16; r++) acc[r] = b;
        for (int q = 0; q < 32; q++) {
            float w0 = A2[(size_t)(4 * q + 0) * 64 + tid];
            float w1 = A2[(size_t)(4 * q + 1) * 64 + tid];
            float w2 = A2[(size_t)(4 * q + 2) * 64 + tid];
            float w3 = A2[(size_t)(4 * q + 3) * 64 + tid];
#pragma unroll
            for (int r = 0; r < 16; r++) {
                float4 zv = *reinterpret_cast<const float4*>(zs + r * 132 + 4 * q);
                acc[r] = fmaf(zv.x, w0, fmaf(zv.y, w1, fmaf(zv.z, w2, fmaf(zv.w, w3, acc[r]))));
            }
        }
#pragma unroll
        for (int r = 0; r < 16; r++) z2[r * 66 + tid] = acc[r];
    }
    __syncthreads();
    if (tid < 32) {
        int lane = tid;
        float a30 = A3v[lane], a31 = A3v[lane + 32];
        float bb = ab3v[0];
        float sloc = 0.f;
        for (int row = 0; row < 16; row++) {
            float v0 = z2[row * 66 + lane];
            float v1 = z2[row * 66 + lane + 32];
            float s = v0 + v1;
            float q = fmaf(v0, v0, v1 * v1);
#pragma unroll
            for (int o = 16; o > 0; o >>= 1) {
                s += __shfl_xor_sync(0xffffffffu, s, o);
                q += __shfl_xor_sync(0xffffffffu, q, o);
            }
            float mu = s / 64.f;
            float var = q / 64.f - mu * mu;
            float rs = rsqrtf(var + EPSV);
            float y0 = fmaxf((v0 - mu) * rs * l2g[lane] + l2b[lane], 0.f);
            float y1 = fmaxf((v1 - mu) * rs * l2g[lane + 32] + l2b[lane + 32], 0.f);
            float t = fmaf(y0, a30, y1 * a31);
#pragma unroll
            for (int o = 16; o > 0; o >>= 1) t += __shfl_xor_sync(0xffffffffu, t, o);
            if (lane == 0) {
                float lg = tanhf(t + bb);
                logits[r0 + row] = lg;
                sloc += expf(lg - 1.f);
            }
        }
        if (lane == 0) atomicAdd(part, sloc);
    }
}

// ---------------- final output: logits + softmax (fixed shift 1) ----------------
__global__ void k_write_out(const float* __restrict__ logits,
                            const float* __restrict__ part, float* __restrict__ out) {
    int i = blockIdx.x * 256 + threadIdx.x;
    if (i < NN) {
        float l = logits[i];
        out[i] = l;
        out[NN + i] = expf(l - 1.f) / part[0];
    }
}

// ---------------- fused GAT softmax + aggregate: one node per block ----------------
template <int C>
__global__ void __launch_bounds__(2 * C) k_gat(
    const __half* __restrict__ h, const float* __restrict__ ls,
    const float* __restrict__ ldv, const int* __restrict__ off,
    const int* __restrict__ srcs, const float* __restrict__ bias,
    float* __restrict__ out) {
    constexpr int CHUNK = 64;
    __shared__ float s_alpha[CHUNK * 4];
    __shared__ int s_srcs[CHUNK];
    __shared__ float s_out[4 * C];
    int n = blockIdx.x;
    int t = threadIdx.x;
    int lane = t & 31;
    int start = off[n], end = off[n + 1];
    float m0 = -FLT_MAX, m1 = -FLT_MAX, m2 = -FLT_MAX, m3 = -FLT_MAX;
    float rd0 = 0.f, rd1 = 0.f, rd2 = 0.f, rd3 = 0.f;
    float ldx = 0.f, ldy = 0.f, ldz = 0.f, ldw = 0.f;
    if (t < 32) {
        float4 ldq = *reinterpret_cast<const float4*>(ldv + n * 4);
        ldx = ldq.x; ldy = ldq.y; ldz = ldq.z; ldw = ldq.w;
        for (int e = start + lane; e < end; e += 32) {
            int s = srcs[e];
            float4 lv = *reinterpret_cast<const float4*>(ls + s * 4);
            m0 = fmaxf(m0, lrelu02(lv.x + ldx));
            m1 = fmaxf(m1, lrelu02(lv.y + ldy));
            m2 = fmaxf(m2, lrelu02(lv.z + ldz));
            m3 = fmaxf(m3, lrelu02(lv.w + ldw));
        }
#pragma unroll
        for (int o = 16; o > 0; o >>= 1) {
            m0 = fmaxf(m0, __shfl_xor_sync(0xffffffffu, m0, o));
            m1 = fmaxf(m1, __shfl_xor_sync(0xffffffffu, m1, o));
            m2 = fmaxf(m2, __shfl_xor_sync(0xffffffffu, m2, o));
            m3 = fmaxf(m3, __shfl_xor_sync(0xffffffffu, m3, o));
        }
        float d0 = 0.f, d1 = 0.f, d2 = 0.f, d3 = 0.f;
        for (int e = start + lane; e < end; e += 32) {
            int s = srcs[e];
            float4 lv = *reinterpret_cast<const float4*>(ls + s * 4);
            d0 += expf(lrelu02(lv.x + ldx) - m0);
            d1 += expf(lrelu02(lv.y + ldy) - m1);
            d2 += expf(lrelu02(lv.z + ldz) - m2);
            d3 += expf(lrelu02(lv.w + ldw) - m3);
        }
#pragma unroll
        for (int o = 16; o > 0; o >>= 1) {
            d0 += __shfl_xor_sync(0xffffffffu, d0, o);
            d1 += __shfl_xor_sync(0xffffffffu, d1, o);
            d2 += __shfl_xor_sync(0xffffffffu, d2, o);
            d3 += __shfl_xor_sync(0xffffffffu, d3, o);
        }
        rd0 = 0.25f / d0; rd1 = 0.25f / d1; rd2 = 0.25f / d2; rd3 = 0.25f / d3;
    }
    int head = t / (C / 2);
    int pair = t % (C / 2);
    float accx = 0.f, accy = 0.f;
    for (int cs = start; cs < end; cs += CHUNK) {
        int ce = min(cs + CHUNK, end);
        if (t < 32) {
            for (int e = cs + lane; e < ce; e += 32) {
                int s = srcs[e];
                float4 lv = *reinterpret_cast<const float4*>(ls + s * 4);
                int i = e - cs;
                s_srcs[i] = s;
                s_alpha[i * 4 + 0] = expf(lrelu02(lv.x + ldx) - m0) * rd0;
                s_alpha[i * 4 + 1] = expf(lrelu02(lv.y + ldy) - m1) * rd1;
                s_alpha[i * 4 + 2] = expf(lrelu02(lv.z + ldz) - m2) * rd2;
                s_alpha[i * 4 + 3] = expf(lrelu02(lv.w + ldw) - m3) * rd3;
            }
        }
        __syncthreads();
        int cnt = ce - cs;
        int i = 0;
        for (; i + 2 <= cnt; i += 2) {
            int s0 = s_srcs[i], s1 = s_srcs[i + 1];
            float a0 = s_alpha[i * 4 + head];
            float a1 = s_alpha[(i + 1) * 4 + head];
            __half2 v0 = *reinterpret_cast<const __half2*>(h + ((size_t)s0 * 4 + head) * C + 2 * pair);
            __half2 v1 = *reinterpret_cast<const __half2*>(h + ((size_t)s1 * 4 + head) * C + 2 * pair);
            float2 f0 = __half22float2(v0), f1 = __half22float2(v1);
            accx = fmaf(f0.x, a0, fmaf(f1.x, a1, accx));
            accy = fmaf(f0.y, a0, fmaf(f1.y, a1, accy));
        }
        if (i < cnt) {
            int s0 = s_srcs[i];
            float a0 = s_alpha[i * 4 + head];
            float2 f0 = __half22float2(
                *reinterpret_cast<const __half2*>(h + ((size_t)s0 * 4 + head) * C + 2 * pair));
            accx = fmaf(f0.x, a0, accx);
            accy = fmaf(f0.y, a0, accy);
        }
        __syncthreads();
    }
    s_out[head * C + 2 * pair] = accx;
    s_out[head * C + 2 * pair + 1] = accy;
    __syncthreads();
    if (t < C) {
        float v = (s_out[t] + s_out[C + t]) + (s_out[2 * C + t] + s_out[3 * C + t]) + bias[t];
        out[(size_t)n * C + t] = v;
    }
}

// ---------------- BN stats ----------------
__global__ void k_bn_stats(const float* __restrict__ x, int N, int C, float* __restrict__ sums) {
    int t = threadIdx.x;
    int r0 = blockIdx.x * 256;
    int r1 = min(r0 + 256, N);
    float s = 0.f, q = 0.f;
    for (int r = r0; r < r1; r++) {
        float v = x[(size_t)r * C + t];
        s += v; q = fmaf(v, v, q);
    }
    atomicAdd(&sums[t], s);
    atomicAdd(&sums[C + t], q);
}

// ---------------- launch ----------------
extern "C" void kernel_launch(void* const* d_in, const int* in_sizes, int n_in,
                              void* d_out, int out_size) {
    const float* x   = (const float*)d_in[0];
    const int* ei    = (const int*)d_in[1];
    int E = in_sizes[1] / 2;
    const int* esrc = ei;
    const int* edst = ei + E;
    const float* W1  = (const float*)d_in[2];
    const float* as1 = (const float*)d_in[3];
    const float* ad1 = (const float*)d_in[4];
    const float* b1  = (const float*)d_in[5];
    const float* g1  = (const float*)d_in[6];
    const float* be1 = (const float*)d_in[7];
    const float* W2  = (const float*)d_in[8];
    const float* as2 = (const float*)d_in[9];
    const float* ad2 = (const float*)d_in[10];
    const float* b2  = (const float*)d_in[11];
    const float* g2  = (const float*)d_in[12];
    const float* be2 = (const float*)d_in[13];
    const float* W3  = (const float*)d_in[14];
    const float* as3 = (const float*)d_in[15];
    const float* ad3 = (const float*)d_in[16];
    const float* b3  = (const float*)d_in[17];
    const float* g3  = (const float*)d_in[18];
    const float* be3 = (const float*)d_in[19];
    const float* A1  = (const float*)d_in[20];
    const float* ab1 = (const float*)d_in[21];
    const float* l1g = (const float*)d_in[22];
    const float* l1b = (const float*)d_in[23];
    const float* A2  = (const float*)d_in[24];
    const float* ab2 = (const float*)d_in[25];
    const float* l2g = (const float*)d_in[26];
    const float* l2b = (const float*)d_in[27];
    const float* A3  = (const float*)d_in[28];
    const float* ab3 = (const float*)d_in[29];

    __half* h;
    float *io0, *io1, *ls, *ld, *logits, *bn, *part;
    int *deg, *off, *cur, *pos, *srcs, *bsum, *bsum2;
    cudaGetSymbolAddress((void**)&h, g_h);
    cudaGetSymbolAddress((void**)&io0, g_io0);
    cudaGetSymbolAddress((void**)&io1, g_io1);
    cudaGetSymbolAddress((void**)&ls, g_ls);
    cudaGetSymbolAddress((void**)&ld, g_ld);
    cudaGetSymbolAddress((void**)&logits, g_logits);
    cudaGetSymbolAddress((void**)&bn, g_bn);
    cudaGetSymbolAddress((void**)&part, g_part);
    cudaGetSymbolAddress((void**)&deg, g_deg);
    cudaGetSymbolAddress((void**)&off, g_off);
    cudaGetSymbolAddress((void**)&cur, g_cur);
    cudaGetSymbolAddress((void**)&pos, g_pos);
    cudaGetSymbolAddress((void**)&srcs, g_srcs);
    cudaGetSymbolAddress((void**)&bsum, g_bsum);
    cudaGetSymbolAddress((void**)&bsum2, g_bsum2);

    unsigned dk[3][2];
    for (unsigned i = 0; i < 3; i++) tf_host(0u, 42u, 0u, i, &dk[i][0], &dk[i][1]);

    const int nb = (NN + 255) / 256;  // 196
    const int NG = NN / 16;           // 3125

    // ---- coef1 + init + selection scan stage1 ----
    k_coef1<<<nb, 256>>>(x, W1, as1, ad1, ls, ld, NN, deg, bn, pos, bsum2, part);

    // ---- CSR build + selection scan stage2 ----
    k_count<<<(E + 255) / 256, 256>>>(edst, E, deg);
    k_scan1<<<nb, 256>>>(deg, off, bsum, NN);
    k_scan2_dual<<<1, 256>>>(bsum, nb, off + NN, bsum2);
    k_scan3<<<nb, 256>>>(off, bsum, cur, deg, NN);   // also zeroes deg (idx buffer)
    k_scatter<<<(E + NN + 255) / 256, 256>>>(esrc, edst, E, NN, cur, srcs);
    k_selfin<<<nb, 256>>>(x, pos, bsum2, deg, NN);

    // ---- layer 1: aggregate-then-project ----
    k_gat1agg<<<(NN + 7) / 8, 256>>>(x, ls, ld, off, srcs, io1);
    k_out1<<<NG, 128>>>(io1, W1, b1, io0, bn);

    // ---- layer 2 ----
    k_gemm<128, 256, 128, 1, 1, 1><<<NG, 128, 16 * 128 * 4>>>(
        io0, 128, 0, nullptr, W2, nullptr, nullptr, h,
        bn, g1, be1, dk[0][0], dk[0][1], as2, ad2, ls, ld);
    k_gat<64><<<NN, 128>>>(h, ls, ld, off, srcs, b2, io1);
    k_bn_stats<<<nb, 64>>>(io1, NN, 64, bn + 256);

    // ---- layer 3 ----
    k_gemm<64, 128, 64, 1, 1, 1><<<NG, 64, 16 * 64 * 4>>>(
        io1, 64, 0, nullptr, W3, nullptr, nullptr, h,
        bn + 256, g2, be2, dk[1][0], dk[1][1], as3, ad3, ls, ld);
    k_gat<32><<<NN, 64>>>(h, ls, ld, off, srcs, b3, io0);
    k_bn_stats<<<nb, 32>>>(io0, NN, 32, bn + 384);

    // ---- merged MLP head (+ exp-sum) ----
    k_head2<<<NG, 64>>>(io0, deg, A1, ab1, l1g, l1b, A2, ab2, l2g, l2b, A3, ab3,
                        bn + 384, g3, be3, dk[2][0], dk[2][1], logits, part);

    // ---- final output ----
    k_write_out<<<nb, 256>>>(logits, part, (float*)d_out);
}

// round 15
// speedup vs baseline: 1.2729x; 1.1236x over previous
#include <cuda_runtime.h>
#include <cuda_fp16.h>
#include <math.h>
#include <float.h>
#include <stdint.h>

#define NN 50000
#define EE 400000
#define EPSV 1e-5f

// ---------------- scratch ----------------
__device__ __half g_h[(size_t)NN * 512];
__device__ float g_io0[(size_t)NN * 128];
__device__ float g_io1[(size_t)NN * 128];   // also reused as agg[NN][16]
__device__ float g_ls[NN * 4];
__device__ float g_ld[NN * 4];
__device__ float g_logits[NN];
__device__ float g_bn[448];
__device__ float g_part[4];     // [0] = sum exp(l-1)
__device__ int   g_deg[NN];     // CSR degree, then reused as selection idx buffer
__device__ int   g_off[NN + 1];
__device__ int   g_cur[NN];
__device__ int   g_pos[NN];     // selection block-local prefix
__device__ int   g_srcs[EE + NN];
__device__ int   g_bsum[256];
__device__ int   g_bsum2[256];

// ---------------- threefry2x32 (partitionable xor bits) ----------------
__device__ __forceinline__ unsigned rotl32d(unsigned v, int r) {
    return __funnelshift_l(v, v, r);
}
__device__ __forceinline__ unsigned tf_xor(unsigned k0, unsigned k1, unsigned x0, unsigned x1) {
    unsigned k2 = k0 ^ k1 ^ 0x1BD11BDAu;
    x0 += k0; x1 += k1;
#define TF_R(r) { x0 += x1; x1 = rotl32d(x1, r); x1 ^= x0; }
    TF_R(13) TF_R(15) TF_R(26) TF_R(6)   x0 += k1; x1 += k2 + 1u;
    TF_R(17) TF_R(29) TF_R(16) TF_R(24)  x0 += k2; x1 += k0 + 2u;
    TF_R(13) TF_R(15) TF_R(26) TF_R(6)   x0 += k0; x1 += k1 + 3u;
    TF_R(17) TF_R(29) TF_R(16) TF_R(24)  x0 += k1; x1 += k2 + 4u;
    TF_R(13) TF_R(15) TF_R(26) TF_R(6)   x0 += k2; x1 += k0 + 5u;
#undef TF_R
    return x0 ^ x1;
}
static inline unsigned rotl32h(unsigned v, int r) { return (v << r) | (v >> (32 - r)); }
static void tf_host(unsigned k0, unsigned k1, unsigned x0, unsigned x1,
                    unsigned* o0, unsigned* o1) {
    unsigned k2 = k0 ^ k1 ^ 0x1BD11BDAu;
    x0 += k0; x1 += k1;
#define TF_RH(r) { x0 += x1; x1 = rotl32h(x1, r); x1 ^= x0; }
    TF_RH(13) TF_RH(15) TF_RH(26) TF_RH(6)   x0 += k1; x1 += k2 + 1u;
    TF_RH(17) TF_RH(29) TF_RH(16) TF_RH(24)  x0 += k2; x1 += k0 + 2u;
    TF_RH(13) TF_RH(15) TF_RH(26) TF_RH(6)   x0 += k0; x1 += k1 + 3u;
    TF_RH(17) TF_RH(29) TF_RH(16) TF_RH(24)  x0 += k1; x1 += k2 + 4u;
    TF_RH(13) TF_RH(15) TF_RH(26) TF_RH(6)   x0 += k2; x1 += k0 + 5u;
#undef TF_RH
    *o0 = x0; *o1 = x1;
}

__global__ void k_count(const int* __restrict__ dst, int e, int* deg) {
    int i = blockIdx.x * blockDim.x + threadIdx.x;
    if (i < e) atomicAdd(&deg[dst[i]], 1);
}

// ---------------- scans ----------------
__global__ void k_scan1(const int* __restrict__ in, int* __restrict__ out,
                        int* __restrict__ bsum, int n) {
    __shared__ int sh[256];
    int i = blockIdx.x * 256 + threadIdx.x;
    int t = threadIdx.x;
    int v = (i < n) ? in[i] : 0;
    sh[t] = v;
    __syncthreads();
#pragma unroll
    for (int o = 1; o < 256; o <<= 1) {
        int add = (t >= o) ? sh[t - o] : 0;
        __syncthreads();
        sh[t] += add;
        __syncthreads();
    }
    if (i < n) out[i] = sh[t] - v;
    if (t == 255) bsum[blockIdx.x] = sh[255];
}
__global__ void k_scan2_dual(int* __restrict__ bsum, int nb, int* __restrict__ total,
                             int* __restrict__ bsum2) {
    __shared__ int sh[256];
    int t = threadIdx.x;
    int v = (t < nb) ? bsum[t] : 0;
    sh[t] = v;
    __syncthreads();
#pragma unroll
    for (int o = 1; o < 256; o <<= 1) {
        int add = (t >= o) ? sh[t - o] : 0;
        __syncthreads();
        sh[t] += add;
        __syncthreads();
    }
    if (t < nb) bsum[t] = sh[t] - v;
    if (t == 0 && total) *total = sh[255];
    __syncthreads();
    int v2 = (t < nb) ? bsum2[t] : 0;
    sh[t] = v2;
    __syncthreads();
#pragma unroll
    for (int o = 1; o < 256; o <<= 1) {
        int add = (t >= o) ? sh[t - o] : 0;
        __syncthreads();
        sh[t] += add;
        __syncthreads();
    }
    if (t < nb) bsum2[t] = sh[t] - v2;
}
__global__ void k_scan3(int* __restrict__ out, const int* __restrict__ bsum,
                        int* __restrict__ cur, int* __restrict__ deg, int n) {
    int i = blockIdx.x * 256 + threadIdx.x;
    if (i < n) {
        int v = out[i] + bsum[blockIdx.x];
        out[i] = v;
        cur[i] = v;
        deg[i] = 0;
    }
}
// scatter (blocks < nsb) + selection scatter (tail blocks)
__global__ void k_scatter_sel(const int* __restrict__ src, const int* __restrict__ dst,
                              int e, int n, int nsb, int* cur, int* __restrict__ outsrc,
                              const float* __restrict__ x, const int* __restrict__ pos,
                              const int* __restrict__ bsum2, int* __restrict__ idx) {
    int b = blockIdx.x;
    if (b < nsb) {
        int i = b * 256 + threadIdx.x;
        if (i < e) {
            int p = atomicAdd(&cur[dst[i]], 1);
            outsrc[p] = src[i];
        } else if (i < e + n) {
            int nd = i - e;
            int p = atomicAdd(&cur[nd], 1);
            outsrc[p] = nd;
        }
    } else {
        int lb = b - nsb;
        int i = lb * 256 + threadIdx.x;
        if (i < n && x[i * 6 + 2] == 1.0f && x[i * 6 + 5] == 0.0f)
            idx[pos[i] + bsum2[lb]] = i;
    }
}

__device__ __forceinline__ float lrelu02(float v) { return v > 0.f ? v : 0.2f * v; }

// ---------------- layer-1 coef + init + selection scan stage1 ----------------
__global__ void k_coef1(const float* __restrict__ x, const float* __restrict__ W1,
                        const float* __restrict__ as1, const float* __restrict__ ad1,
                        float* __restrict__ ls, float* __restrict__ ld, int n,
                        int* __restrict__ deg, float* __restrict__ bnz,
                        int* __restrict__ pos, int* __restrict__ bsum2,
                        float* __restrict__ part) {
    __shared__ float fold[32];
    __shared__ int sh[256];
    int t = threadIdx.x;
    int i = blockIdx.x * 256 + t;
    if (i < n) deg[i] = 1;
    if (i < 448) bnz[i] = 0.f;
    if (i == 0) part[0] = 0.f;
    int c = 0;
    float x0 = 0.f, x1 = 0.f, x2 = 0.f, x3 = 0.f;
    if (i < n) {
        x0 = x[i * 6 + 1]; x1 = x[i * 6 + 2]; x2 = x[i * 6 + 3]; x3 = x[i * 6 + 4];
        c = (x1 == 1.0f && x[i * 6 + 5] == 0.0f) ? 1 : 0;
    }
    sh[t] = c;
    if (t < 32) {
        int h = (t & 15) >> 2, k = t & 3;
        const float* a = (t < 16) ? as1 : ad1;
        float s = 0.f;
        for (int cc = 0; cc < 128; cc++)
            s = fmaf(W1[k * 512 + h * 128 + cc], a[h * 128 + cc], s);
        fold[t] = s;
    }
    __syncthreads();
#pragma unroll
    for (int o = 1; o < 256; o <<= 1) {
        int add = (t >= o) ? sh[t - o] : 0;
        __syncthreads();
        sh[t] += add;
        __syncthreads();
    }
    if (i < n) pos[i] = sh[t] - c;
    if (t == 255) bsum2[blockIdx.x] = sh[255];
    if (i >= n) return;
#pragma unroll
    for (int h = 0; h < 4; h++) {
        float s = fmaf(x0, fold[h * 4 + 0], fmaf(x1, fold[h * 4 + 1],
                  fmaf(x2, fold[h * 4 + 2], x3 * fold[h * 4 + 3])));
        float d = fmaf(x0, fold[16 + h * 4 + 0], fmaf(x1, fold[16 + h * 4 + 1],
                  fmaf(x2, fold[16 + h * 4 + 2], x3 * fold[16 + h * 4 + 3])));
        ls[i * 4 + h] = s;
        ld[i * 4 + h] = d;
    }
}

// ---------------- layer-1 aggregate in input space: warp per dst node ----------------
__global__ void __launch_bounds__(256) k_gat1agg(
    const float* __restrict__ x, const float* __restrict__ ls,
    const float* __restrict__ ldv, const int* __restrict__ off,
    const int* __restrict__ srcs, float* __restrict__ agg) {
    int n = blockIdx.x * 8 + (threadIdx.x >> 5);
    int lane = threadIdx.x & 31;
    if (n >= NN) return;
    int start = off[n], end = off[n + 1];
    float4 ldq = *reinterpret_cast<const float4*>(ldv + n * 4);
    float m0 = -FLT_MAX, m1 = -FLT_MAX, m2 = -FLT_MAX, m3 = -FLT_MAX;
    for (int e = start + lane; e < end; e += 32) {
        int s = srcs[e];
        float4 lv = *reinterpret_cast<const float4*>(ls + s * 4);
        m0 = fmaxf(m0, lrelu02(lv.x + ldq.x));
        m1 = fmaxf(m1, lrelu02(lv.y + ldq.y));
        m2 = fmaxf(m2, lrelu02(lv.z + ldq.z));
        m3 = fmaxf(m3, lrelu02(lv.w + ldq.w));
    }
#pragma unroll
    for (int o = 16; o > 0; o >>= 1) {
        m0 = fmaxf(m0, __shfl_xor_sync(0xffffffffu, m0, o));
        m1 = fmaxf(m1, __shfl_xor_sync(0xffffffffu, m1, o));
        m2 = fmaxf(m2, __shfl_xor_sync(0xffffffffu, m2, o));
        m3 = fmaxf(m3, __shfl_xor_sync(0xffffffffu, m3, o));
    }
    float d0 = 0.f, d1 = 0.f, d2 = 0.f, d3 = 0.f;
    for (int e = start + lane; e < end; e += 32) {
        int s = srcs[e];
        float4 lv = *reinterpret_cast<const float4*>(ls + s * 4);
        d0 += expf(lrelu02(lv.x + ldq.x) - m0);
        d1 += expf(lrelu02(lv.y + ldq.y) - m1);
        d2 += expf(lrelu02(lv.z + ldq.z) - m2);
        d3 += expf(lrelu02(lv.w + ldq.w) - m3);
    }
#pragma unroll
    for (int o = 16; o > 0; o >>= 1) {
        d0 += __shfl_xor_sync(0xffffffffu, d0, o);
        d1 += __shfl_xor_sync(0xffffffffu, d1, o);
        d2 += __shfl_xor_sync(0xffffffffu, d2, o);
        d3 += __shfl_xor_sync(0xffffffffu, d3, o);
    }
    float rd0 = 0.25f / d0, rd1 = 0.25f / d1, rd2 = 0.25f / d2, rd3 = 0.25f / d3;
    float acc[16];
#pragma unroll
    for (int i = 0; i < 16; i++) acc[i] = 0.f;
    for (int e = start + lane; e < end; e += 32) {
        int s = srcs[e];
        float4 lv = *reinterpret_cast<const float4*>(ls + s * 4);
        float a0 = expf(lrelu02(lv.x + ldq.x) - m0) * rd0;
        float a1 = expf(lrelu02(lv.y + ldq.y) - m1) * rd1;
        float a2 = expf(lrelu02(lv.z + ldq.z) - m2) * rd2;
        float a3 = expf(lrelu02(lv.w + ldq.w) - m3) * rd3;
        const float* xr = x + (size_t)s * 6 + 1;
        float xv0 = xr[0], xv1 = xr[1], xv2 = xr[2], xv3 = xr[3];
        acc[0]  = fmaf(a0, xv0, acc[0]);  acc[1]  = fmaf(a0, xv1, acc[1]);
        acc[2]  = fmaf(a0, xv2, acc[2]);  acc[3]  = fmaf(a0, xv3, acc[3]);
        acc[4]  = fmaf(a1, xv0, acc[4]);  acc[5]  = fmaf(a1, xv1, acc[5]);
        acc[6]  = fmaf(a1, xv2, acc[6]);  acc[7]  = fmaf(a1, xv3, acc[7]);
        acc[8]  = fmaf(a2, xv0, acc[8]);  acc[9]  = fmaf(a2, xv1, acc[9]);
        acc[10] = fmaf(a2, xv2, acc[10]); acc[11] = fmaf(a2, xv3, acc[11]);
        acc[12] = fmaf(a3, xv0, acc[12]); acc[13] = fmaf(a3, xv1, acc[13]);
        acc[14] = fmaf(a3, xv2, acc[14]); acc[15] = fmaf(a3, xv3, acc[15]);
    }
#pragma unroll
    for (int i = 0; i < 16; i++) {
#pragma unroll
        for (int o = 16; o > 0; o >>= 1)
            acc[i] += __shfl_xor_sync(0xffffffffu, acc[i], o);
    }
    if (lane == 0) {
#pragma unroll
        for (int i = 0; i < 16; i++) agg[(size_t)n * 16 + i] = acc[i];
    }
}

// ---------------- layer-1 output projection + fused BN stats ----------------
__global__ void __launch_bounds__(128) k_out1(
    const float* __restrict__ agg, const float* __restrict__ W1,
    const float* __restrict__ b1, float* __restrict__ out, float* __restrict__ bnsum) {
    __shared__ float sA[256];
    int r0 = blockIdx.x * 16;
    int t = threadIdx.x;
    for (int i = t; i < 256; i += 128) sA[i] = agg[(size_t)r0 * 16 + i];
    __syncthreads();
    float w[16];
#pragma unroll
    for (int h = 0; h < 4; h++)
#pragma unroll
        for (int k = 0; k < 4; k++)
            w[h * 4 + k] = W1[k * 512 + h * 128 + t];
    float b = b1[t];
    float s = 0.f, q = 0.f;
#pragma unroll
    for (int r = 0; r < 16; r++) {
        float acc = b;
#pragma unroll
        for (int i = 0; i < 16; i++) acc = fmaf(sA[r * 16 + i], w[i], acc);
        out[(size_t)(r0 + r) * 128 + t] = acc;
        s += acc;
        q = fmaf(acc, acc, q);
    }
    atomicAdd(&bnsum[t], s);
    atomicAdd(&bnsum[128 + t], q);
}

// ---------------- fused GEMM (R10 config) ----------------
template <int KK, int MM, int BD, int PRE, int POST, int COEF>
__global__ void __launch_bounds__(BD) k_gemm(
    const float* __restrict__ X, int ldx, int xcol0, const int* __restrict__ gidx,
    const float* __restrict__ W, const float* __restrict__ bias,
    float* __restrict__ Yf, __half* __restrict__ Yh,
    const float* __restrict__ bnsum, const float* __restrict__ bng,
    const float* __restrict__ bnbe, unsigned key0, unsigned key1,
    const float* __restrict__ as_, const float* __restrict__ ad_,
    float* __restrict__ lsout, float* __restrict__ ldout) {
    static_assert(MM == 2 * BD, "MM must be 2*BD");
    extern __shared__ float xs[];
    __shared__ float red[16][8];
    int r0 = blockIdx.x * 16;
    int tid = threadIdx.x;
    const float invN = 1.f / (float)NN;
    if (COEF) {
        for (int i = tid; i < 128; i += BD) red[i >> 3][i & 7] = 0.f;
    }
    for (int i = tid; i < 16 * KK; i += BD) {
        int r = i & 15, k = i >> 4;
        int row = r0 + r;
        int srow = (gidx != nullptr) ? gidx[row] : row;
        float v = X[(size_t)srow * ldx + xcol0 + k];
        if (PRE > 0) {
            float mu = bnsum[k] * invN;
            float var = bnsum[KK + k] * invN - mu * mu;
            v = (v - mu) * rsqrtf(var + EPSV) * bng[k] + bnbe[k];
            if (PRE == 1) v = v > 0.f ? v : expm1f(v);
            unsigned bits = tf_xor(key0, key1, 0u, (unsigned)(srow * KK + k));
            v = (bits & 0x80000000u) ? 0.f : 2.f * v;
        }
        xs[k * 16 + r] = v;
    }
    __syncthreads();
    int j0 = tid, j1 = tid + BD;
    float acc0[16], acc1[16];
    float b0 = bias ? bias[j0] : 0.f;
    float b1 = bias ? bias[j1] : 0.f;
#pragma unroll
    for (int r = 0; r < 16; r++) { acc0[r] = b0; acc1[r] = b1; }
#pragma unroll 4
    for (int k = 0; k < KK; k++) {
        float w0 = W[(size_t)k * MM + j0];
        float w1 = W[(size_t)k * MM + j1];
        const float4* xp = reinterpret_cast<const float4*>(xs + k * 16);
        float4 q0 = xp[0], q1 = xp[1], q2 = xp[2], q3 = xp[3];
        float xv[16] = {q0.x, q0.y, q0.z, q0.w, q1.x, q1.y, q1.z, q1.w,
                        q2.x, q2.y, q2.z, q2.w, q3.x, q3.y, q3.z, q3.w};
#pragma unroll
        for (int r = 0; r < 16; r++) {
            acc0[r] = fmaf(xv[r], w0, acc0[r]);
            acc1[r] = fmaf(xv[r], w1, acc1[r]);
        }
    }
    if (POST == 1) {
#pragma unroll
        for (int r = 0; r < 16; r++) {
            Yh[(size_t)(r0 + r) * MM + j0] = __float2half_rn(acc0[r]);
            Yh[(size_t)(r0 + r) * MM + j1] = __float2half_rn(acc1[r]);
        }
    }
    if (COEF) {
        constexpr int C = MM / 4;
        int hd0 = j0 / C, hd1 = j1 / C;
        float as0 = as_[hd0 * C + (j0 % C)], ad0 = ad_[hd0 * C + (j0 % C)];
        float as1v = as_[hd1 * C + (j1 % C)], ad1v = ad_[hd1 * C + (j1 % C)];
        int lane = tid & 31;
#pragma unroll
        for (int r = 0; r < 16; r++) {
            float vs0 = acc0[r] * as0;
            float vd0 = acc0[r] * ad0;
            float vs1 = acc1[r] * as1v;
            float vd1 = acc1[r] * ad1v;
#pragma unroll
            for (int o = 16; o > 0; o >>= 1) {
                vs0 += __shfl_xor_sync(0xffffffffu, vs0, o);
                vd0 += __shfl_xor_sync(0xffffffffu, vd0, o);
                vs1 += __shfl_xor_sync(0xffffffffu, vs1, o);
                vd1 += __shfl_xor_sync(0xffffffffu, vd1, o);
            }
            if (lane == 0) {
                atomicAdd(&red[r][hd0], vs0);
                atomicAdd(&red[r][4 + hd0], vd0);
                atomicAdd(&red[r][hd1], vs1);
                atomicAdd(&red[r][4 + hd1], vd1);
            }
        }
        __syncthreads();
        if (tid < 64) {
            int r = tid >> 2, hd = tid & 3;
            lsout[(r0 + r) * 4 + hd] = red[r][hd];
            ldout[(r0 + r) * 4 + hd] = red[r][4 + hd];
        }
    }
}

// ---------------- warp-per-node GAT softmax + aggregate (no smem, no syncs) ----------------
// C=64: each lane loads 1 uint4 (8 halves) per edge; C=32: 1 uint2 (4 halves).
template <int C>
__global__ void __launch_bounds__(256) k_gatw(
    const __half* __restrict__ h, const float* __restrict__ ls,
    const float* __restrict__ ldv, const int* __restrict__ off,
    const int* __restrict__ srcs, const float* __restrict__ bias,
    float* __restrict__ out) {
    constexpr int HPL = C / 8;            // halves per lane (8 for C=64, 4 for C=32)
    constexpr int FPL = HPL;              // float accumulators per lane
    int n = blockIdx.x * 8 + (threadIdx.x >> 5);
    int lane = threadIdx.x & 31;
    if (n >= NN) return;
    int start = off[n], end = off[n + 1];
    float4 ldq = *reinterpret_cast<const float4*>(ldv + n * 4);
    // pass 1: max (strided, all lanes)
    float m0 = -FLT_MAX, m1 = -FLT_MAX, m2 = -FLT_MAX, m3 = -FLT_MAX;
    for (int e = start + lane; e < end; e += 32) {
        int s = srcs[e];
        float4 lv = *reinterpret_cast<const float4*>(ls + s * 4);
        m0 = fmaxf(m0, lrelu02(lv.x + ldq.x));
        m1 = fmaxf(m1, lrelu02(lv.y + ldq.y));
        m2 = fmaxf(m2, lrelu02(lv.z + ldq.z));
        m3 = fmaxf(m3, lrelu02(lv.w + ldq.w));
    }
#pragma unroll
    for (int o = 16; o > 0; o >>= 1) {
        m0 = fmaxf(m0, __shfl_xor_sync(0xffffffffu, m0, o));
        m1 = fmaxf(m1, __shfl_xor_sync(0xffffffffu, m1, o));
        m2 = fmaxf(m2, __shfl_xor_sync(0xffffffffu, m2, o));
        m3 = fmaxf(m3, __shfl_xor_sync(0xffffffffu, m3, o));
    }
    // pass 2: denom (strided)
    float d0 = 0.f, d1 = 0.f, d2 = 0.f, d3 = 0.f;
    for (int e = start + lane; e < end; e += 32) {
        int s = srcs[e];
        float4 lv = *reinterpret_cast<const float4*>(ls + s * 4);
        d0 += expf(lrelu02(lv.x + ldq.x) - m0);
        d1 += expf(lrelu02(lv.y + ldq.y) - m1);
        d2 += expf(lrelu02(lv.z + ldq.z) - m2);
        d3 += expf(lrelu02(lv.w + ldq.w) - m3);
    }
#pragma unroll
    for (int o = 16; o > 0; o >>= 1) {
        d0 += __shfl_xor_sync(0xffffffffu, d0, o);
        d1 += __shfl_xor_sync(0xffffffffu, d1, o);
        d2 += __shfl_xor_sync(0xffffffffu, d2, o);
        d3 += __shfl_xor_sync(0xffffffffu, d3, o);
    }
    float rd0 = 0.25f / d0, rd1 = 0.25f / d1, rd2 = 0.25f / d2, rd3 = 0.25f / d3;
    // per-lane head selection (lanes 0-3 compute alpha for heads 0-3)
    int head = lane >> 3;
    float mh = (lane == 0) ? m0 : (lane == 1) ? m1 : (lane == 2) ? m2 : m3;
    float dh = (lane == 0) ? rd0 : (lane == 1) ? rd1 : (lane == 2) ? rd2 : rd3;
    float lh = (lane == 0) ? ldq.x : (lane == 1) ? ldq.y : (lane == 2) ? ldq.z : ldq.w;
    // pass 3: accumulate (warp processes one edge at a time)
    float acc[FPL];
#pragma unroll
    for (int i = 0; i < FPL; i++) acc[i] = 0.f;
    const __half* hb = h + (size_t)0;
    for (int e = start; e < end; e++) {
        int s = srcs[e];
        float a = 0.f;
        if (lane < 4) a = expf(lrelu02(ls[s * 4 + lane] + lh) - mh) * dh;
        a = __shfl_sync(0xffffffffu, a, head);
        const __half* hr = hb + ((size_t)s * 4 + head) * C + (lane & 7) * HPL;
        if (C == 64) {
            uint4 v = *reinterpret_cast<const uint4*>(hr);
            __half2 p0 = *reinterpret_cast<__half2*>(&v.x);
            __half2 p1 = *reinterpret_cast<__half2*>(&v.y);
            __half2 p2 = *reinterpret_cast<__half2*>(&v.z);
            __half2 p3 = *reinterpret_cast<__half2*>(&v.w);
            float2 f0 = __half22float2(p0), f1 = __half22float2(p1);
            float2 f2 = __half22float2(p2), f3 = __half22float2(p3);
            acc[0] = fmaf(f0.x, a, acc[0]); acc[1] = fmaf(f0.y, a, acc[1]);
            acc[2] = fmaf(f1.x, a, acc[2]); acc[3] = fmaf(f1.y, a, acc[3]);
            acc[4] = fmaf(f2.x, a, acc[4]); acc[5] = fmaf(f2.y, a, acc[5]);
            acc[6] = fmaf(f3.x, a, acc[6]); acc[7] = fmaf(f3.y, a, acc[7]);
        } else {
            uint2 v = *reinterpret_cast<const uint2*>(hr);
            __half2 p0 = *reinterpret_cast<__half2*>(&v.x);
            __half2 p1 = *reinterpret_cast<__half2*>(&v.y);
            float2 f0 = __half22float2(p0), f1 = __half22float2(p1);
            acc[0] = fmaf(f0.x, a, acc[0]); acc[1] = fmaf(f0.y, a, acc[1]);
            acc[2] = fmaf(f1.x, a, acc[2]); acc[3] = fmaf(f1.y, a, acc[3]);
        }
    }
    // cross-head reduction: lanes l, l^8, l^16, l^24 hold same channels
#pragma unroll
    for (int i = 0; i < FPL; i++) {
        acc[i] += __shfl_xor_sync(0xffffffffu, acc[i], 8);
        acc[i] += __shfl_xor_sync(0xffffffffu, acc[i], 16);
    }
    if (lane < 8) {
        int c0 = lane * HPL;
#pragma unroll
        for (int i = 0; i < FPL; i++)
            out[(size_t)n * C + c0 + i] = acc[i] + bias[c0 + i];
    }
}

// ---------------- merged MLP head + exp-sum accumulation ----------------
__global__ void __launch_bounds__(64) k_head2(
    const float* __restrict__ X, const int* __restrict__ gidx,
    const float* __restrict__ A1, const float* __restrict__ ab1,
    const float* __restrict__ l1g, const float* __restrict__ l1b,
    const float* __restrict__ A2, const float* __restrict__ ab2,
    const float* __restrict__ l2g, const float* __restrict__ l2b,
    const float* __restrict__ A3v, const float* __restrict__ ab3v,
    const float* __restrict__ bnsum, const float* __restrict__ bng,
    const float* __restrict__ bnbe, unsigned key0, unsigned key1,
    float* __restrict__ logits, float* __restrict__ part) {
    __shared__ float sx[32 * 16];
    __shared__ float zs[16 * 132];
    __shared__ float z2[16 * 66];
    int r0 = blockIdx.x * 16;
    int tid = threadIdx.x;
    const float invN = 1.f / (float)NN;
    for (int i = tid; i < 16 * 32; i += 64) {
        int r = i & 15, k = i >> 4;
        int srow = gidx[r0 + r];
        float v = X[(size_t)srow * 32 + k];
        float mu = bnsum[k] * invN;
        float var = bnsum[32 + k] * invN - mu * mu;
        v = (v - mu) * rsqrtf(var + EPSV) * bng[k] + bnbe[k];
        unsigned bits = tf_xor(key0, key1, 0u, (unsigned)(srow * 32 + k));
        v = (bits & 0x80000000u) ? 0.f : 2.f * v;
        sx[k * 16 + r] = v;
    }
    __syncthreads();
    {
        int j0 = tid, j1 = tid + 64;
        float acc0[16], acc1[16];
        float b0 = ab1[j0], b1 = ab1[j1];
#pragma unroll
        for (int r = 0; r < 16; r++) { acc0[r] = b0; acc1[r] = b1; }
#pragma unroll 4
        for (int k = 0; k < 32; k++) {
            float w0 = A1[(size_t)k * 128 + j0];
            float w1 = A1[(size_t)k * 128 + j1];
            const float4* xp = reinterpret_cast<const float4*>(sx + k * 16);
            float4 q0 = xp[0], q1 = xp[1], q2 = xp[2], q3 = xp[3];
            float xv[16] = {q0.x, q0.y, q0.z, q0.w, q1.x, q1.y, q1.z, q1.w,
                            q2.x, q2.y, q2.z, q2.w, q3.x, q3.y, q3.z, q3.w};
#pragma unroll
            for (int r = 0; r < 16; r++) {
                acc0[r] = fmaf(xv[r], w0, acc0[r]);
                acc1[r] = fmaf(xv[r], w1, acc1[r]);
            }
        }
#pragma unroll
        for (int r = 0; r < 16; r++) {
            zs[r * 132 + j0] = acc0[r];
            zs[r * 132 + j1] = acc1[r];
        }
    }
    __syncthreads();
    {
        int w = tid >> 5, lane = tid & 31;
        for (int row = w; row < 16; row += 2) {
            float v[4];
            float s = 0.f, q = 0.f;
#pragma unroll
            for (int i = 0; i < 4; i++) {
                v[i] = zs[row * 132 + lane + 32 * i];
                s += v[i]; q = fmaf(v[i], v[i], q);
            }
#pragma unroll
            for (int o = 16; o > 0; o >>= 1) {
                s += __shfl_xor_sync(0xffffffffu, s, o);
                q += __shfl_xor_sync(0xffffffffu, q, o);
            }
            float mu = s / 128.f;
            float var = q / 128.f - mu * mu;
            float rs = rsqrtf(var + EPSV);
#pragma unroll
            for (int i = 0; i < 4; i++) {
                int c = lane + 32 * i;
                float y = (v[i] - mu) * rs * l1g[c] + l1b[c];
                zs[row * 132 + c] = fmaxf(y, 0.f);
            }
        }
    }
    __syncthreads();
    {
        float acc[16];
        float b = ab2[tid];
#pragma unroll
        for (int r = 0; r < 16; r++) acc[r] = b;
        for (int q = 0; q < 32; q++) {
            float w0 = A2[(size_t)(4 * q + 0) * 64 + tid];
            float w1 = A2[(size_t)(4 * q + 1) * 64 + tid];
            float w2 = A2[(size_t)(4 * q + 2) * 64 + tid];
            float w3 = A2[(size_t)(4 * q + 3) * 64 + tid];
#pragma unroll
            for (int r = 0; r < 16; r++) {
                float4 zv = *reinterpret_cast<const float4*>(zs + r * 132 + 4 * q);
                acc[r] = fmaf(zv.x, w0, fmaf(zv.y, w1, fmaf(zv.z, w2, fmaf(zv.w, w3, acc[r]))));
            }
        }
#pragma unroll
        for (int r = 0; r < 16; r++) z2[r * 66 + tid] = acc[r];
    }
    __syncthreads();
    if (tid < 32) {
        int lane = tid;
        float a30 = A3v[lane], a31 = A3v[lane + 32];
        float bb = ab3v[0];
        float sloc = 0.f;
        for (int row = 0; row < 16; row++) {
            float v0 = z2[row * 66 + lane];
            float v1 = z2[row * 66 + lane + 32];
            float s = v0 + v1;
            float q = fmaf(v0, v0, v1 * v1);
#pragma unroll
            for (int o = 16; o > 0; o >>= 1) {
                s += __shfl_xor_sync(0xffffffffu, s, o);
                q += __shfl_xor_sync(0xffffffffu, q, o);
            }
            float mu = s / 64.f;
            float var = q / 64.f - mu * mu;
            float rs = rsqrtf(var + EPSV);
            float y0 = fmaxf((v0 - mu) * rs * l2g[lane] + l2b[lane], 0.f);
            float y1 = fmaxf((v1 - mu) * rs * l2g[lane + 32] + l2b[lane + 32], 0.f);
            float t = fmaf(y0, a30, y1 * a31);
#pragma unroll
            for (int o = 16; o > 0; o >>= 1) t += __shfl_xor_sync(0xffffffffu, t, o);
            if (lane == 0) {
                float lg = tanhf(t + bb);
                logits[r0 + row] = lg;
                sloc += expf(lg - 1.f);
            }
        }
        if (lane == 0) atomicAdd(part, sloc);
    }
}

// ---------------- final output ----------------
__global__ void k_write_out(const float* __restrict__ logits,
                            const float* __restrict__ part, float* __restrict__ out) {
    int i = blockIdx.x * 256 + threadIdx.x;
    if (i < NN) {
        float l = logits[i];
        out[i] = l;
        out[NN + i] = expf(l - 1.f) / part[0];
    }
}

// ---------------- BN stats ----------------
__global__ void k_bn_stats(const float* __restrict__ x, int N, int C, float* __restrict__ sums) {
    int t = threadIdx.x;
    int r0 = blockIdx.x * 256;
    int r1 = min(r0 + 256, N);
    float s = 0.f, q = 0.f;
    for (int r = r0; r < r1; r++) {
        float v = x[(size_t)r * C + t];
        s += v; q = fmaf(v, v, q);
    }
    atomicAdd(&sums[t], s);
    atomicAdd(&sums[C + t], q);
}

// ---------------- launch ----------------
extern "C" void kernel_launch(void* const* d_in, const int* in_sizes, int n_in,
                              void* d_out, int out_size) {
    const float* x   = (const float*)d_in[0];
    const int* ei    = (const int*)d_in[1];
    int E = in_sizes[1] / 2;
    const int* esrc = ei;
    const int* edst = ei + E;
    const float* W1  = (const float*)d_in[2];
    const float* as1 = (const float*)d_in[3];
    const float* ad1 = (const float*)d_in[4];
    const float* b1  = (const float*)d_in[5];
    const float* g1  = (const float*)d_in[6];
    const float* be1 = (const float*)d_in[7];
    const float* W2  = (const float*)d_in[8];
    const float* as2 = (const float*)d_in[9];
    const float* ad2 = (const float*)d_in[10];
    const float* b2  = (const float*)d_in[11];
    const float* g2  = (const float*)d_in[12];
    const float* be2 = (const float*)d_in[13];
    const float* W3  = (const float*)d_in[14];
    const float* as3 = (const float*)d_in[15];
    const float* ad3 = (const float*)d_in[16];
    const float* b3  = (const float*)d_in[17];
    const float* g3  = (const float*)d_in[18];
    const float* be3 = (const float*)d_in[19];
    const float* A1  = (const float*)d_in[20];
    const float* ab1 = (const float*)d_in[21];
    const float* l1g = (const float*)d_in[22];
    const float* l1b = (const float*)d_in[23];
    const float* A2  = (const float*)d_in[24];
    const float* ab2 = (const float*)d_in[25];
    const float* l2g = (const float*)d_in[26];
    const float* l2b = (const float*)d_in[27];
    const float* A3  = (const float*)d_in[28];
    const float* ab3 = (const float*)d_in[29];

    __half* h;
    float *io0, *io1, *ls, *ld, *logits, *bn, *part;
    int *deg, *off, *cur, *pos, *srcs, *bsum, *bsum2;
    cudaGetSymbolAddress((void**)&h, g_h);
    cudaGetSymbolAddress((void**)&io0, g_io0);
    cudaGetSymbolAddress((void**)&io1, g_io1);
    cudaGetSymbolAddress((void**)&ls, g_ls);
    cudaGetSymbolAddress((void**)&ld, g_ld);
    cudaGetSymbolAddress((void**)&logits, g_logits);
    cudaGetSymbolAddress((void**)&bn, g_bn);
    cudaGetSymbolAddress((void**)&part, g_part);
    cudaGetSymbolAddress((void**)&deg, g_deg);
    cudaGetSymbolAddress((void**)&off, g_off);
    cudaGetSymbolAddress((void**)&cur, g_cur);
    cudaGetSymbolAddress((void**)&pos, g_pos);
    cudaGetSymbolAddress((void**)&srcs, g_srcs);
    cudaGetSymbolAddress((void**)&bsum, g_bsum);
    cudaGetSymbolAddress((void**)&bsum2, g_bsum2);

    unsigned dk[3][2];
    for (unsigned i = 0; i < 3; i++) tf_host(0u, 42u, 0u, i, &dk[i][0], &dk[i][1]);

    const int nb = (NN + 255) / 256;  // 196
    const int NG = NN / 16;           // 3125
    const int nsb = (E + NN + 255) / 256;

    // ---- coef1 + init + selection scan stage1 ----
    k_coef1<<<nb, 256>>>(x, W1, as1, ad1, ls, ld, NN, deg, bn, pos, bsum2, part);

    // ---- CSR build + selection scan stage2 + selection scatter (merged tail) ----
    k_count<<<(E + 255) / 256, 256>>>(edst, E, deg);
    k_scan1<<<nb, 256>>>(deg, off, bsum, NN);
    k_scan2_dual<<<1, 256>>>(bsum, nb, off + NN, bsum2);
    k_scan3<<<nb, 256>>>(off, bsum, cur, deg, NN);
    k_scatter_sel<<<nsb + nb, 256>>>(esrc, edst, E, NN, nsb, cur, srcs,
                                     x, pos, bsum2, deg);

    // ---- layer 1: aggregate-then-project ----
    k_gat1agg<<<(NN + 7) / 8, 256>>>(x, ls, ld, off, srcs, io1);
    k_out1<<<NG, 128>>>(io1, W1, b1, io0, bn);

    // ---- layer 2 ----
    k_gemm<128, 256, 128, 1, 1, 1><<<NG, 128, 16 * 128 * 4>>>(
        io0, 128, 0, nullptr, W2, nullptr, nullptr, h,
        bn, g1, be1, dk[0][0], dk[0][1], as2, ad2, ls, ld);
    k_gatw<64><<<(NN + 7) / 8, 256>>>(h, ls, ld, off, srcs, b2, io1);
    k_bn_stats<<<nb, 64>>>(io1, NN, 64, bn + 256);

    // ---- layer 3 ----
    k_gemm<64, 128, 64, 1, 1, 1><<<NG, 64, 16 * 64 * 4>>>(
        io1, 64, 0, nullptr, W3, nullptr, nullptr, h,
        bn + 256, g2, be2, dk[1][0], dk[1][1], as3, ad3, ls, ld);
    k_gatw<32><<<(NN + 7) / 8, 256>>>(h, ls, ld, off, srcs, b3, io0);
    k_bn_stats<<<nb, 32>>>(io0, NN, 32, bn + 384);

    // ---- merged MLP head (+ exp-sum) ----
    k_head2<<<NG, 64>>>(io0, deg, A1, ab1, l1g, l1b, A2, ab2, l2g, l2b, A3, ab3,
                        bn + 384, g3, be3, dk[2][0], dk[2][1], logits, part);

    // ---- final output ----
    k_write_out<<<nb, 256>>>(logits, part, (float*)d_out);
}